// round 1
// baseline (speedup 1.0000x reference)
#include <cuda_runtime.h>
#include <cstddef>

// ---------------- problem constants ----------------
#define B_ROWS 16384
#define F_CAT  26
#define N_NUM  13
#define D_EMB  32
#define KDIM   1248   // (26+13)*32
#define H1     256
#define H2     128
#define H3     64
#define VOCAB  100000

// ---------------- scratch (static device memory; no runtime allocs) --------
// layout: e [B*KDIM] | h1 [B*H1] | h2 [B*H2] | h3 [B*H3] | lin [B] | fm [B]
#define OFF_E   ((size_t)0)
#define OFF_H1  (OFF_E  + (size_t)B_ROWS * KDIM)
#define OFF_H2  (OFF_H1 + (size_t)B_ROWS * H1)
#define OFF_H3  (OFF_H2 + (size_t)B_ROWS * H2)
#define OFF_LIN (OFF_H3 + (size_t)B_ROWS * H3)
#define OFF_FM  (OFF_LIN + (size_t)B_ROWS)
#define SCRATCH_FLOATS (OFF_FM + (size_t)B_ROWS)

__device__ float g_scratch[SCRATCH_FLOATS];

// ---------------- warp reduce ----------------
__device__ __forceinline__ float warp_sum(float v) {
    #pragma unroll
    for (int o = 16; o > 0; o >>= 1)
        v += __shfl_down_sync(0xffffffffu, v, o);
    return v;
}

// ---------------- kernel 1: embedding gather + FM + linear ----------------
// one warp per batch row. lane == embedding dim d (0..31).
__global__ void embed_kernel(const int*   __restrict__ x_cat,
                             const float* __restrict__ x_num,
                             const float* __restrict__ emb0,
                             const float* __restrict__ emb1,
                             const float* __restrict__ num_bias,
                             const float* __restrict__ num_emb,
                             float* __restrict__ e_out,    // [B, KDIM]
                             float* __restrict__ lin_out,  // [B]
                             float* __restrict__ fm_out)   // [B]
{
    int gw   = (blockIdx.x * blockDim.x + threadIdx.x) >> 5;
    int lane = threadIdx.x & 31;
    if (gw >= B_ROWS) return;
    const int b = gw;

    // preload this row's categorical indices (lanes 0..25) and numerics (0..12)
    int   myid = (lane < F_CAT) ? x_cat[(size_t)b * F_CAT + lane] : 0;
    float myx  = (lane < N_NUM) ? x_num[(size_t)b * N_NUM + lane] : 0.0f;

    float* erow = e_out + (size_t)b * KDIM;

    float sum_d = 0.0f, sq_d = 0.0f;
    // linear term partials
    float lin_p = 0.0f;
    if (lane < F_CAT) lin_p += emb0[(size_t)lane * VOCAB + myid];
    if (lane < N_NUM) lin_p += myx * num_bias[lane];

    // categorical embeddings: emb1[f, id, :]
    #pragma unroll
    for (int f = 0; f < F_CAT; f++) {
        int id  = __shfl_sync(0xffffffffu, myid, f);
        float v = emb1[((size_t)f * VOCAB + id) * D_EMB + lane];
        sum_d += v;
        sq_d  += v * v;
        erow[f * D_EMB + lane] = v;
    }
    // numeric embeddings: x_num[b,n] * num_emb[n,:]
    #pragma unroll
    for (int n = 0; n < N_NUM; n++) {
        float xv = __shfl_sync(0xffffffffu, myx, n);
        float v  = xv * num_emb[n * D_EMB + lane];
        sum_d += v;
        sq_d  += v * v;
        erow[(F_CAT + n) * D_EMB + lane] = v;
    }

    float fm  = 0.5f * warp_sum(sum_d * sum_d - sq_d);
    float lin = warp_sum(lin_p);
    if (lane == 0) {
        lin_out[b] = lin;
        fm_out[b]  = fm;
    }
}

// ---------------- generic fp32 register-tiled GEMM: C = act(A @ W + bias) --
// A: M x K row-major, W: K x N row-major, C: M x N row-major.
// All dims assumed multiples of the tile sizes (true for this problem).
template<int BM, int BN, int BK, int TM, int TN, bool RELU>
__global__ __launch_bounds__((BM/TM)*(BN/TN))
void gemm_bias_act(const float* __restrict__ A,
                   const float* __restrict__ W,
                   const float* __restrict__ bias,
                   float* __restrict__ C,
                   int M, int N, int K)
{
    constexpr int THREADS = (BM / TM) * (BN / TN);
    __shared__ float As[BK][BM + 4];   // transposed A tile (+pad vs conflicts)
    __shared__ float Bs[BK][BN];

    const int tid  = threadIdx.x;
    const int tRow = tid / (BN / TN);
    const int tCol = tid % (BN / TN);

    const float* Ablk = A + (size_t)blockIdx.y * BM * K;
    const float* Wblk = W + (size_t)blockIdx.x * BN;

    float acc[TM][TN];
    #pragma unroll
    for (int i = 0; i < TM; i++)
        #pragma unroll
        for (int j = 0; j < TN; j++) acc[i][j] = 0.0f;

    for (int k0 = 0; k0 < K; k0 += BK) {
        // load A tile (BM x BK), store transposed
        #pragma unroll
        for (int i = tid * 4; i < BM * BK; i += THREADS * 4) {
            int r = i / BK, c = i % BK;
            float4 v = *reinterpret_cast<const float4*>(Ablk + (size_t)r * K + k0 + c);
            As[c + 0][r] = v.x;
            As[c + 1][r] = v.y;
            As[c + 2][r] = v.z;
            As[c + 3][r] = v.w;
        }
        // load W tile (BK x BN)
        #pragma unroll
        for (int i = tid * 4; i < BK * BN; i += THREADS * 4) {
            int r = i / BN, c = i % BN;
            *reinterpret_cast<float4*>(&Bs[r][c]) =
                *reinterpret_cast<const float4*>(Wblk + (size_t)(k0 + r) * N + c);
        }
        __syncthreads();

        #pragma unroll
        for (int kk = 0; kk < BK; kk++) {
            float ra[TM], rb[TN];
            #pragma unroll
            for (int i = 0; i < TM; i += 4) {
                float4 v = *reinterpret_cast<const float4*>(&As[kk][tRow * TM + i]);
                ra[i + 0] = v.x; ra[i + 1] = v.y; ra[i + 2] = v.z; ra[i + 3] = v.w;
            }
            #pragma unroll
            for (int j = 0; j < TN; j += 4) {
                float4 v = *reinterpret_cast<const float4*>(&Bs[kk][tCol * TN + j]);
                rb[j + 0] = v.x; rb[j + 1] = v.y; rb[j + 2] = v.z; rb[j + 3] = v.w;
            }
            #pragma unroll
            for (int i = 0; i < TM; i++)
                #pragma unroll
                for (int j = 0; j < TN; j++)
                    acc[i][j] = fmaf(ra[i], rb[j], acc[i][j]);
        }
        __syncthreads();
    }

    // epilogue: bias + optional relu
    #pragma unroll
    for (int i = 0; i < TM; i++) {
        int r = blockIdx.y * BM + tRow * TM + i;
        #pragma unroll
        for (int j = 0; j < TN; j++) {
            int c = blockIdx.x * BN + tCol * TN + j;
            float v = acc[i][j] + bias[c];
            if (RELU) v = fmaxf(v, 0.0f);
            C[(size_t)r * N + c] = v;
        }
    }
}

// ---------------- kernel 5: head (two 66-dim dots per row) ----------------
// one warp per batch row; lane covers h3 dims (lane, lane+32).
__global__ void head_kernel(const float* __restrict__ h3,   // [B, 64]
                            const float* __restrict__ lin,  // [B]
                            const float* __restrict__ fm,   // [B]
                            const float* __restrict__ Wc,   // [66]
                            const float* __restrict__ bc,   // [1]
                            const float* __restrict__ Wo,   // [66]
                            const float* __restrict__ bo,   // [1]
                            float* __restrict__ out)        // [2*B]: logit1 | logit2
{
    int gw   = (blockIdx.x * blockDim.x + threadIdx.x) >> 5;
    int lane = threadIdx.x & 31;
    if (gw >= B_ROWS) return;
    const int b = gw;

    float h0 = h3[(size_t)b * H3 + lane];
    float h1v = h3[(size_t)b * H3 + 32 + lane];

    float dc = h0 * Wc[lane] + h1v * Wc[32 + lane];
    float dw = h0 * Wo[lane] + h1v * Wo[32 + lane];
    dc = warp_sum(dc);
    dw = warp_sum(dw);

    if (lane == 0) {
        float l = lin[b], f = fm[b];
        out[b]          = dc + l * Wc[64] + f * Wc[65] + bc[0];
        out[B_ROWS + b] = dw + l * Wo[64] + f * Wo[65] + bo[0];
    }
}

// ---------------- launch ----------------
extern "C" void kernel_launch(void* const* d_in, const int* in_sizes, int n_in,
                              void* d_out, int out_size)
{
    const int*   x_cat    = (const int*)  d_in[0];
    const float* x_num    = (const float*)d_in[1];
    const float* emb0     = (const float*)d_in[2];
    const float* emb1     = (const float*)d_in[3];
    const float* num_bias = (const float*)d_in[4];
    const float* num_emb  = (const float*)d_in[5];
    const float* W1       = (const float*)d_in[6];
    const float* b1       = (const float*)d_in[7];
    const float* W2       = (const float*)d_in[8];
    const float* b2       = (const float*)d_in[9];
    const float* W3       = (const float*)d_in[10];
    const float* b3       = (const float*)d_in[11];
    const float* Wc       = (const float*)d_in[12];
    const float* bc       = (const float*)d_in[13];
    const float* Wo       = (const float*)d_in[14];
    const float* bo       = (const float*)d_in[15];
    float* out = (float*)d_out;

    float* base = nullptr;
    cudaGetSymbolAddress((void**)&base, g_scratch);
    float* e   = base + OFF_E;
    float* h1  = base + OFF_H1;
    float* h2  = base + OFF_H2;
    float* h3  = base + OFF_H3;
    float* lin = base + OFF_LIN;
    float* fm  = base + OFF_FM;

    // 1) embedding gather + FM/linear  (8 warps per 256-thread block)
    embed_kernel<<<B_ROWS / 8, 256>>>(x_cat, x_num, emb0, emb1, num_bias,
                                      num_emb, e, lin, fm);

    // 2) h1 = relu(e @ W1 + b1)   [16384 x 1248] @ [1248 x 256]
    gemm_bias_act<128, 128, 16, 8, 8, true>
        <<<dim3(H1 / 128, B_ROWS / 128), 256>>>(e, W1, b1, h1, B_ROWS, H1, KDIM);

    // 3) h2 = relu(h1 @ W2 + b2)  [16384 x 256] @ [256 x 128]
    gemm_bias_act<128, 128, 16, 8, 8, true>
        <<<dim3(H2 / 128, B_ROWS / 128), 256>>>(h1, W2, b2, h2, B_ROWS, H2, H1);

    // 4) h3 = relu(h2 @ W3 + b3)  [16384 x 128] @ [128 x 64]
    gemm_bias_act<128, 64, 16, 8, 4, true>
        <<<dim3(H3 / 64, B_ROWS / 128), 256>>>(h2, W3, b3, h3, B_ROWS, H3, H2);

    // 5) head: two logits per row
    head_kernel<<<B_ROWS / 8, 256>>>(h3, lin, fm, Wc, bc, Wo, bo, out);
}

// round 3
// speedup vs baseline: 1.5802x; 1.5802x over previous
#include <cuda_runtime.h>
#include <cuda_bf16.h>
#include <cstdint>
#include <cstddef>

typedef __nv_bfloat16 bf16;

// ---------------- problem constants ----------------
#define B_ROWS 16384
#define F_CAT  26
#define N_NUM  13
#define VOCAB  100000
#define K1     1248
#define K1P    1280   // padded to multiple of 64
#define H1     256
#define H2     128
#define H3     64

// ---------------- scratch (static device memory) ----------------
constexpr size_t ALN(size_t x) { return (x + 255) & ~(size_t)255; }
constexpr size_t OFF_EHI = 0;
constexpr size_t SZ_E    = (size_t)B_ROWS * K1P * 2;              // bf16
constexpr size_t OFF_ELO = ALN(OFF_EHI + SZ_E);
constexpr size_t OFF_W1T = ALN(OFF_ELO + SZ_E);                   // [256][3840] bf16
constexpr size_t OFF_W2T = ALN(OFF_W1T + (size_t)H1 * 3 * K1P * 2);
constexpr size_t OFF_W3T = ALN(OFF_W2T + (size_t)H2 * 3 * H1 * 2);
constexpr size_t OFF_H1H = ALN(OFF_W3T + (size_t)H3 * 3 * H2 * 2);
constexpr size_t OFF_H1L = ALN(OFF_H1H + (size_t)B_ROWS * H1 * 2);
constexpr size_t OFF_H2H = ALN(OFF_H1L + (size_t)B_ROWS * H1 * 2);
constexpr size_t OFF_H2L = ALN(OFF_H2H + (size_t)B_ROWS * H2 * 2);
constexpr size_t OFF_H3  = ALN(OFF_H2L + (size_t)B_ROWS * H2 * 2);
constexpr size_t OFF_LIN = ALN(OFF_H3  + (size_t)B_ROWS * H3 * 4);
constexpr size_t OFF_FM  = ALN(OFF_LIN + (size_t)B_ROWS * 4);
constexpr size_t TOTAL_SCRATCH = ALN(OFF_FM + (size_t)B_ROWS * 4);

__device__ __align__(256) unsigned char g_scratch[TOTAL_SCRATCH];

// ---------------- PTX helpers (sm_80-compatible; no 'a' features) ----------
__device__ __forceinline__ uint32_t smem_to_u32(const void* p) {
    uint32_t a;
    asm("{ .reg .u64 t; cvta.to.shared.u64 t, %1; cvt.u32.u64 %0, t; }" : "=r"(a) : "l"(p));
    return a;
}

__device__ __forceinline__ void cp_async16(uint32_t saddr, const void* gaddr) {
    asm volatile("cp.async.cg.shared.global [%0], [%1], 16;"
                 :: "r"(saddr), "l"(gaddr) : "memory");
}
__device__ __forceinline__ void cp_commit() {
    asm volatile("cp.async.commit_group;" ::: "memory");
}
template<int N>
__device__ __forceinline__ void cp_wait() {
    asm volatile("cp.async.wait_group %0;" :: "n"(N) : "memory");
}

__device__ __forceinline__ void ldsm_x4(uint32_t& r0, uint32_t& r1,
                                        uint32_t& r2, uint32_t& r3, uint32_t addr) {
    asm volatile("ldmatrix.sync.aligned.m8n8.x4.shared.b16 {%0,%1,%2,%3}, [%4];"
                 : "=r"(r0), "=r"(r1), "=r"(r2), "=r"(r3) : "r"(addr));
}

// D = A*B + D ; m16n8k16, bf16 in, f32 accum
__device__ __forceinline__ void mma16816(float* d, const uint32_t* a, const uint32_t* b) {
    asm volatile(
        "mma.sync.aligned.m16n8k16.row.col.f32.bf16.bf16.f32 "
        "{%0,%1,%2,%3}, {%4,%5,%6,%7}, {%8,%9}, {%0,%1,%2,%3};"
        : "+f"(d[0]), "+f"(d[1]), "+f"(d[2]), "+f"(d[3])
        : "r"(a[0]), "r"(a[1]), "r"(a[2]), "r"(a[3]), "r"(b[0]), "r"(b[1]));
}

// ---------------- warp reduce ----------------
__device__ __forceinline__ float warp_sum(float v) {
    #pragma unroll
    for (int o = 16; o > 0; o >>= 1) v += __shfl_down_sync(0xffffffffu, v, o);
    return v;
}

// ---------------- kernel 1: embedding gather + FM + linear (bf16 hi/lo out) --
__global__ void embed_kernel(const int*   __restrict__ x_cat,
                             const float* __restrict__ x_num,
                             const float* __restrict__ emb0,
                             const float* __restrict__ emb1,
                             const float* __restrict__ num_bias,
                             const float* __restrict__ num_emb,
                             bf16* __restrict__ e_hi,   // [B, K1P]
                             bf16* __restrict__ e_lo,   // [B, K1P]
                             float* __restrict__ lin_out,
                             float* __restrict__ fm_out)
{
    int gw   = (blockIdx.x * blockDim.x + threadIdx.x) >> 5;
    int lane = threadIdx.x & 31;
    if (gw >= B_ROWS) return;
    const int b = gw;

    int   myid = (lane < F_CAT) ? x_cat[(size_t)b * F_CAT + lane] : 0;
    float myx  = (lane < N_NUM) ? x_num[(size_t)b * N_NUM + lane] : 0.0f;

    bf16* hrow = e_hi + (size_t)b * K1P;
    bf16* lrow = e_lo + (size_t)b * K1P;

    float sum_d = 0.0f, sq_d = 0.0f, lin_p = 0.0f;
    if (lane < F_CAT) lin_p += emb0[(size_t)lane * VOCAB + myid];
    if (lane < N_NUM) lin_p += myx * num_bias[lane];

    #pragma unroll
    for (int f = 0; f < F_CAT; f++) {
        int id  = __shfl_sync(0xffffffffu, myid, f);
        float v = emb1[((size_t)f * VOCAB + id) * 32 + lane];
        sum_d += v; sq_d += v * v;
        bf16 h = __float2bfloat16(v);
        hrow[f * 32 + lane] = h;
        lrow[f * 32 + lane] = __float2bfloat16(v - __bfloat162float(h));
    }
    #pragma unroll
    for (int n = 0; n < N_NUM; n++) {
        float xv = __shfl_sync(0xffffffffu, myx, n);
        float v  = xv * num_emb[n * 32 + lane];
        sum_d += v; sq_d += v * v;
        bf16 h = __float2bfloat16(v);
        hrow[(F_CAT + n) * 32 + lane] = h;
        lrow[(F_CAT + n) * 32 + lane] = __float2bfloat16(v - __bfloat162float(h));
    }
    bf16 z = __float2bfloat16(0.0f);
    hrow[K1 + lane] = z;
    lrow[K1 + lane] = z;

    float fm  = 0.5f * warp_sum(sum_d * sum_d - sq_d);
    float lin = warp_sum(lin_p);
    if (lane == 0) { lin_out[b] = lin; fm_out[b] = fm; }
}

// ---------------- prep: W' = transposed, 3-segment split weights ----------
// out[n][s*seglen + c] : s=0 -> hi(W[c][n]), s=1 -> lo(W[c][n]), s=2 -> hi(W[c][n])
__global__ void prep_wt(const float* __restrict__ W, bf16* __restrict__ out,
                        int K, int N, int seglen)
{
    int idx = blockIdx.x * blockDim.x + threadIdx.x;
    int tot = N * 3 * seglen;
    if (idx >= tot) return;
    int n = idx / (3 * seglen);
    int r = idx % (3 * seglen);
    int s = r / seglen;
    int c = r % seglen;
    bf16 res = __float2bfloat16(0.0f);
    if (c < K) {
        float w  = W[(size_t)c * N + n];
        bf16 hi  = __float2bfloat16(w);
        res = (s == 1) ? __float2bfloat16(w - __bfloat162float(hi)) : hi;
    }
    out[idx] = res;
}

// ---------------- mma.sync GEMM: out = relu(A @ W + bias) -------------------
// A given as (a_hi, a_lo) bf16, K-extended segments [hi, hi, lo]; W' arranged
// [N][3*lda] bf16 (segments hi, lo, hi). Block tile: 128 x BN, BK = 32.
// Warp grid 2 x (BN/32), warp tile 64 x 32, m16n8k16 HMMA, 3-stage cp.async.
template<int BN, bool SPLIT_OUT>
__global__ __launch_bounds__(64 * (BN / 32))
void gemm_mma(const bf16* __restrict__ a_hi, const bf16* __restrict__ a_lo, const int lda,
              const bf16* __restrict__ wt,  const int ldw,
              const float* __restrict__ bias,
              bf16* __restrict__ out_hi, bf16* __restrict__ out_lo,
              float* __restrict__ out_f32, const int ldo)
{
    constexpr int WN      = BN / 32;
    constexpr int THREADS = 64 * WN;
    constexpr int ROWB    = 80;                // padded smem row stride (bytes)
    constexpr int A_BYTES = 128 * ROWB;        // 10240
    constexpr int B_BYTES = BN * ROWB;
    constexpr int STAGE   = A_BYTES + B_BYTES;
    constexpr int A_IT    = (128 * 4) / THREADS;
    constexpr int B_IT    = (BN * 4) / THREADS;

    extern __shared__ unsigned char smem[];
    const uint32_t sbase = smem_to_u32(smem);

    const int tid  = threadIdx.x;
    const int wid  = tid >> 5;
    const int lid  = tid & 31;
    const int wm   = wid / WN;                 // 0..1
    const int wn   = wid % WN;                 // 0..WN-1

    const int mrow0 = blockIdx.y * 128;
    const int nb0   = blockIdx.x * BN;
    const int nchunks = (3 * lda) / 32;

    // per-thread gmem/smem mapping for tile loads
    const int a_r  = tid >> 2, a_c = tid & 3;          // row, 16B-chunk
    const uint32_t a_sm_off = (uint32_t)a_r * ROWB + (uint32_t)a_c * 16;
    const bf16* wrow = wt + (size_t)(nb0 + a_r) * ldw + a_c * 8;

    auto issue_tile = [&](int c, int buf) {
        const int kc  = c * 32;
        const int s   = kc / lda;
        const int col = kc - s * lda;
        const bf16* asrc = (s == 2 ? a_lo : a_hi) + (size_t)mrow0 * lda + col;
        uint32_t As = sbase + buf * STAGE;
        #pragma unroll
        for (int i = 0; i < A_IT; i++) {
            int r = a_r + i * (THREADS / 4);
            cp_async16(As + a_sm_off + i * (THREADS / 4) * ROWB,
                       asrc + (size_t)r * lda + a_c * 8);
        }
        uint32_t Bs = sbase + buf * STAGE + A_BYTES;
        #pragma unroll
        for (int i = 0; i < B_IT; i++) {
            cp_async16(Bs + a_sm_off + i * (THREADS / 4) * ROWB,
                       wrow + (size_t)i * (THREADS / 4) * ldw + kc);
        }
        cp_commit();
    };

    float acc[4][4][4];
    #pragma unroll
    for (int i = 0; i < 4; i++)
        #pragma unroll
        for (int j = 0; j < 4; j++)
            #pragma unroll
            for (int k = 0; k < 4; k++) acc[i][j][k] = 0.0f;

    // prologue: stages 0, 1
    issue_tile(0, 0);
    issue_tile(1, 1);

    // lane bases for ldmatrix (row = .. + (lid&15), chunk = (lid>>4))
    const uint32_t a_lane = (uint32_t)(wm * 64 + (lid & 15)) * ROWB + (uint32_t)(lid >> 4) * 16;
    const uint32_t b_lane = (uint32_t)(wn * 32 + (lid & 15)) * ROWB + (uint32_t)(lid >> 4) * 16;

    for (int c = 0; c < nchunks; c++) {
        const int buf = c % 3;
        cp_wait<1>();
        __syncthreads();
        if (c + 2 < nchunks) issue_tile(c + 2, (c + 2) % 3);
        else cp_commit();                       // keep group count in lockstep

        const uint32_t As = sbase + buf * STAGE + a_lane;
        const uint32_t Bs = sbase + buf * STAGE + A_BYTES + b_lane;

        #pragma unroll
        for (int ks = 0; ks < 2; ks++) {
            uint32_t af[4][4];
            #pragma unroll
            for (int mi = 0; mi < 4; mi++)
                ldsm_x4(af[mi][0], af[mi][1], af[mi][2], af[mi][3],
                        As + mi * 16 * ROWB + ks * 32);
            uint32_t bf_[4][2];
            #pragma unroll
            for (int j = 0; j < 2; j++) {
                uint32_t r0, r1, r2, r3;
                ldsm_x4(r0, r1, r2, r3, Bs + j * 16 * ROWB + ks * 32);
                bf_[j * 2 + 0][0] = r0; bf_[j * 2 + 0][1] = r2;
                bf_[j * 2 + 1][0] = r1; bf_[j * 2 + 1][1] = r3;
            }
            #pragma unroll
            for (int mi = 0; mi < 4; mi++)
                #pragma unroll
                for (int ni = 0; ni < 4; ni++)
                    mma16816(acc[mi][ni], af[mi], bf_[ni]);
        }
        __syncthreads();
    }

    // epilogue: bias + relu from fragments, direct global stores
    #pragma unroll
    for (int mi = 0; mi < 4; mi++) {
        #pragma unroll
        for (int ni = 0; ni < 4; ni++) {
            const int m0 = mrow0 + wm * 64 + mi * 16 + (lid >> 2);
            const int n0 = nb0 + wn * 32 + ni * 8 + (lid & 3) * 2;
            const float b0 = __ldg(&bias[n0]);
            const float b1 = __ldg(&bias[n0 + 1]);
            float v00 = fmaxf(acc[mi][ni][0] + b0, 0.0f);
            float v01 = fmaxf(acc[mi][ni][1] + b1, 0.0f);
            float v10 = fmaxf(acc[mi][ni][2] + b0, 0.0f);
            float v11 = fmaxf(acc[mi][ni][3] + b1, 0.0f);
            if (SPLIT_OUT) {
                bf16 h00 = __float2bfloat16(v00), h01 = __float2bfloat16(v01);
                bf16 h10 = __float2bfloat16(v10), h11 = __float2bfloat16(v11);
                __nv_bfloat162 hp0; hp0.x = h00; hp0.y = h01;
                __nv_bfloat162 hp1; hp1.x = h10; hp1.y = h11;
                __nv_bfloat162 lp0;
                lp0.x = __float2bfloat16(v00 - __bfloat162float(h00));
                lp0.y = __float2bfloat16(v01 - __bfloat162float(h01));
                __nv_bfloat162 lp1;
                lp1.x = __float2bfloat16(v10 - __bfloat162float(h10));
                lp1.y = __float2bfloat16(v11 - __bfloat162float(h11));
                *reinterpret_cast<__nv_bfloat162*>(out_hi + (size_t)m0 * ldo + n0) = hp0;
                *reinterpret_cast<__nv_bfloat162*>(out_hi + (size_t)(m0 + 8) * ldo + n0) = hp1;
                *reinterpret_cast<__nv_bfloat162*>(out_lo + (size_t)m0 * ldo + n0) = lp0;
                *reinterpret_cast<__nv_bfloat162*>(out_lo + (size_t)(m0 + 8) * ldo + n0) = lp1;
            } else {
                *reinterpret_cast<float2*>(out_f32 + (size_t)m0 * ldo + n0) =
                    make_float2(v00, v01);
                *reinterpret_cast<float2*>(out_f32 + (size_t)(m0 + 8) * ldo + n0) =
                    make_float2(v10, v11);
            }
        }
    }
}

// ---------------- head: two 66-dim dots per row ----------------
__global__ void head_kernel(const float* __restrict__ h3,
                            const float* __restrict__ lin,
                            const float* __restrict__ fm,
                            const float* __restrict__ Wc, const float* __restrict__ bc,
                            const float* __restrict__ Wo, const float* __restrict__ bo,
                            float* __restrict__ out)
{
    int gw   = (blockIdx.x * blockDim.x + threadIdx.x) >> 5;
    int lane = threadIdx.x & 31;
    if (gw >= B_ROWS) return;
    const int b = gw;

    float h0 = h3[(size_t)b * H3 + lane];
    float h1v = h3[(size_t)b * H3 + 32 + lane];

    float dc = h0 * Wc[lane] + h1v * Wc[32 + lane];
    float dw = h0 * Wo[lane] + h1v * Wo[32 + lane];
    dc = warp_sum(dc);
    dw = warp_sum(dw);

    if (lane == 0) {
        float l = lin[b], f = fm[b];
        out[b]          = dc + l * Wc[64] + f * Wc[65] + bc[0];
        out[B_ROWS + b] = dw + l * Wo[64] + f * Wo[65] + bo[0];
    }
}

// ---------------- launch ----------------
extern "C" void kernel_launch(void* const* d_in, const int* in_sizes, int n_in,
                              void* d_out, int out_size)
{
    const int*   x_cat    = (const int*)  d_in[0];
    const float* x_num    = (const float*)d_in[1];
    const float* emb0     = (const float*)d_in[2];
    const float* emb1     = (const float*)d_in[3];
    const float* num_bias = (const float*)d_in[4];
    const float* num_emb  = (const float*)d_in[5];
    const float* W1 = (const float*)d_in[6];
    const float* b1 = (const float*)d_in[7];
    const float* W2 = (const float*)d_in[8];
    const float* b2 = (const float*)d_in[9];
    const float* W3 = (const float*)d_in[10];
    const float* b3 = (const float*)d_in[11];
    const float* Wc = (const float*)d_in[12];
    const float* bc = (const float*)d_in[13];
    const float* Wo = (const float*)d_in[14];
    const float* bo = (const float*)d_in[15];
    float* out = (float*)d_out;

    unsigned char* base = nullptr;
    cudaGetSymbolAddress((void**)&base, g_scratch);
    bf16*  e_hi = (bf16*)(base + OFF_EHI);
    bf16*  e_lo = (bf16*)(base + OFF_ELO);
    bf16*  w1t  = (bf16*)(base + OFF_W1T);
    bf16*  w2t  = (bf16*)(base + OFF_W2T);
    bf16*  w3t  = (bf16*)(base + OFF_W3T);
    bf16*  h1h  = (bf16*)(base + OFF_H1H);
    bf16*  h1l  = (bf16*)(base + OFF_H1L);
    bf16*  h2h  = (bf16*)(base + OFF_H2H);
    bf16*  h2l  = (bf16*)(base + OFF_H2L);
    float* h3   = (float*)(base + OFF_H3);
    float* lin  = (float*)(base + OFF_LIN);
    float* fm   = (float*)(base + OFF_FM);

    // smem: 3 stages of (A 10240B + B BN*80B)
    constexpr int SMEM_128 = 3 * (10240 + 128 * 80);   // 61440
    constexpr int SMEM_64  = 3 * (10240 + 64 * 80);    // 46080
    cudaFuncSetAttribute(gemm_mma<128, true>,
                         cudaFuncAttributeMaxDynamicSharedMemorySize, SMEM_128);
    cudaFuncSetAttribute(gemm_mma<64, false>,
                         cudaFuncAttributeMaxDynamicSharedMemorySize, SMEM_64);

    // 0) weight prep (3-segment transposed bf16 splits)
    prep_wt<<<(H1 * 3 * K1P + 255) / 256, 256>>>(W1, w1t, K1, H1, K1P);
    prep_wt<<<(H2 * 3 * H1  + 255) / 256, 256>>>(W2, w2t, H1, H2, H1);
    prep_wt<<<(H3 * 3 * H2  + 255) / 256, 256>>>(W3, w3t, H2, H3, H2);

    // 1) embedding gather + FM/linear (bf16 hi/lo output)
    embed_kernel<<<B_ROWS / 8, 256>>>(x_cat, x_num, emb0, emb1, num_bias,
                                      num_emb, e_hi, e_lo, lin, fm);

    // 2) h1 = relu(e @ W1 + b1)   K' = 3840
    gemm_mma<128, true><<<dim3(H1 / 128, B_ROWS / 128), 256, SMEM_128>>>(
        e_hi, e_lo, K1P, w1t, 3 * K1P, b1, h1h, h1l, nullptr, H1);

    // 3) h2 = relu(h1 @ W2 + b2)  K' = 768
    gemm_mma<128, true><<<dim3(H2 / 128, B_ROWS / 128), 256, SMEM_128>>>(
        h1h, h1l, H1, w2t, 3 * H1, b2, h2h, h2l, nullptr, H2);

    // 4) h3 = relu(h2 @ W3 + b3)  K' = 384, fp32 out
    gemm_mma<64, false><<<dim3(H3 / 64, B_ROWS / 128), 128, SMEM_64>>>(
        h2h, h2l, H2, w3t, 3 * H2, b3, nullptr, nullptr, h3, H3);

    // 5) head
    head_kernel<<<B_ROWS / 8, 256>>>(h3, lin, fm, Wc, bc, Wo, bo, out);
}

// round 4
// speedup vs baseline: 1.7212x; 1.0892x over previous
#include <cuda_runtime.h>
#include <cuda_bf16.h>
#include <cstdint>
#include <cstddef>

typedef __nv_bfloat16 bf16;

// ---------------- problem constants ----------------
#define B_ROWS 16384
#define F_CAT  26
#define N_NUM  13
#define VOCAB  100000
#define K1     1248
#define K1P    1280   // padded to multiple of 64
#define H1     256
#define H2     128
#define H3     64

// ---------------- scratch (static device memory) ----------------
constexpr size_t ALN(size_t x) { return (x + 255) & ~(size_t)255; }
constexpr size_t OFF_EHI = 0;
constexpr size_t SZ_E    = (size_t)B_ROWS * K1P * 2;              // bf16
constexpr size_t OFF_ELO = ALN(OFF_EHI + SZ_E);
constexpr size_t OFF_W1T = ALN(OFF_ELO + SZ_E);                   // [256][3840] bf16
constexpr size_t OFF_W2T = ALN(OFF_W1T + (size_t)H1 * 3 * K1P * 2);
constexpr size_t OFF_W3T = ALN(OFF_W2T + (size_t)H2 * 3 * H1 * 2);
constexpr size_t OFF_H1H = ALN(OFF_W3T + (size_t)H3 * 3 * H2 * 2);
constexpr size_t OFF_H1L = ALN(OFF_H1H + (size_t)B_ROWS * H1 * 2);
constexpr size_t OFF_H2H = ALN(OFF_H1L + (size_t)B_ROWS * H1 * 2);
constexpr size_t OFF_H2L = ALN(OFF_H2H + (size_t)B_ROWS * H2 * 2);
constexpr size_t OFF_H3  = ALN(OFF_H2L + (size_t)B_ROWS * H2 * 2);
constexpr size_t OFF_LIN = ALN(OFF_H3  + (size_t)B_ROWS * H3 * 4);
constexpr size_t OFF_FM  = ALN(OFF_LIN + (size_t)B_ROWS * 4);
constexpr size_t TOTAL_SCRATCH = ALN(OFF_FM + (size_t)B_ROWS * 4);

__device__ __align__(256) unsigned char g_scratch[TOTAL_SCRATCH];

// ---------------- PTX helpers (sm_80-compatible; no 'a' features) ----------
__device__ __forceinline__ uint32_t smem_to_u32(const void* p) {
    uint32_t a;
    asm("{ .reg .u64 t; cvta.to.shared.u64 t, %1; cvt.u32.u64 %0, t; }" : "=r"(a) : "l"(p));
    return a;
}

__device__ __forceinline__ void cp_async16(uint32_t saddr, const void* gaddr) {
    asm volatile("cp.async.cg.shared.global [%0], [%1], 16;"
                 :: "r"(saddr), "l"(gaddr) : "memory");
}
__device__ __forceinline__ void cp_commit() {
    asm volatile("cp.async.commit_group;" ::: "memory");
}
template<int N>
__device__ __forceinline__ void cp_wait() {
    asm volatile("cp.async.wait_group %0;" :: "n"(N) : "memory");
}

__device__ __forceinline__ void ldsm_x4(uint32_t& r0, uint32_t& r1,
                                        uint32_t& r2, uint32_t& r3, uint32_t addr) {
    asm volatile("ldmatrix.sync.aligned.m8n8.x4.shared.b16 {%0,%1,%2,%3}, [%4];"
                 : "=r"(r0), "=r"(r1), "=r"(r2), "=r"(r3) : "r"(addr));
}

// D = A*B + D ; m16n8k16, bf16 in, f32 accum
__device__ __forceinline__ void mma16816(float* d, const uint32_t* a, const uint32_t* b) {
    asm volatile(
        "mma.sync.aligned.m16n8k16.row.col.f32.bf16.bf16.f32 "
        "{%0,%1,%2,%3}, {%4,%5,%6,%7}, {%8,%9}, {%0,%1,%2,%3};"
        : "+f"(d[0]), "+f"(d[1]), "+f"(d[2]), "+f"(d[3])
        : "r"(a[0]), "r"(a[1]), "r"(a[2]), "r"(a[3]), "r"(b[0]), "r"(b[1]));
}

// ---------------- warp reduce ----------------
__device__ __forceinline__ float warp_sum(float v) {
    #pragma unroll
    for (int o = 16; o > 0; o >>= 1) v += __shfl_down_sync(0xffffffffu, v, o);
    return v;
}

// ---------------- kernel 1: embedding gather + FM + linear (bf16 hi/lo out) --
__global__ void embed_kernel(const int*   __restrict__ x_cat,
                             const float* __restrict__ x_num,
                             const float* __restrict__ emb0,
                             const float* __restrict__ emb1,
                             const float* __restrict__ num_bias,
                             const float* __restrict__ num_emb,
                             bf16* __restrict__ e_hi,   // [B, K1P]
                             bf16* __restrict__ e_lo,   // [B, K1P]
                             float* __restrict__ lin_out,
                             float* __restrict__ fm_out)
{
    int gw   = (blockIdx.x * blockDim.x + threadIdx.x) >> 5;
    int lane = threadIdx.x & 31;
    if (gw >= B_ROWS) return;
    const int b = gw;

    int   myid = (lane < F_CAT) ? x_cat[(size_t)b * F_CAT + lane] : 0;
    float myx  = (lane < N_NUM) ? x_num[(size_t)b * N_NUM + lane] : 0.0f;

    bf16* hrow = e_hi + (size_t)b * K1P;
    bf16* lrow = e_lo + (size_t)b * K1P;

    float sum_d = 0.0f, sq_d = 0.0f, lin_p = 0.0f;
    if (lane < F_CAT) lin_p += emb0[(size_t)lane * VOCAB + myid];
    if (lane < N_NUM) lin_p += myx * num_bias[lane];

    #pragma unroll
    for (int f = 0; f < F_CAT; f++) {
        int id  = __shfl_sync(0xffffffffu, myid, f);
        float v = emb1[((size_t)f * VOCAB + id) * 32 + lane];
        sum_d += v; sq_d += v * v;
        bf16 h = __float2bfloat16(v);
        hrow[f * 32 + lane] = h;
        lrow[f * 32 + lane] = __float2bfloat16(v - __bfloat162float(h));
    }
    #pragma unroll
    for (int n = 0; n < N_NUM; n++) {
        float xv = __shfl_sync(0xffffffffu, myx, n);
        float v  = xv * num_emb[n * 32 + lane];
        sum_d += v; sq_d += v * v;
        bf16 h = __float2bfloat16(v);
        hrow[(F_CAT + n) * 32 + lane] = h;
        lrow[(F_CAT + n) * 32 + lane] = __float2bfloat16(v - __bfloat162float(h));
    }
    bf16 z = __float2bfloat16(0.0f);
    hrow[K1 + lane] = z;
    lrow[K1 + lane] = z;

    float fm  = 0.5f * warp_sum(sum_d * sum_d - sq_d);
    float lin = warp_sum(lin_p);
    if (lane == 0) { lin_out[b] = lin; fm_out[b] = fm; }
}

// ---------------- prep: W' = transposed, 3-segment split weights ----------
// out[n][s*seglen + c] : s=0 -> hi(W[c][n]), s=1 -> lo(W[c][n]), s=2 -> hi(W[c][n])
__global__ void prep_wt(const float* __restrict__ W, bf16* __restrict__ out,
                        int K, int N, int seglen)
{
    int idx = blockIdx.x * blockDim.x + threadIdx.x;
    int tot = N * 3 * seglen;
    if (idx >= tot) return;
    int n = idx / (3 * seglen);
    int r = idx % (3 * seglen);
    int s = r / seglen;
    int c = r % seglen;
    bf16 res = __float2bfloat16(0.0f);
    if (c < K) {
        float w  = W[(size_t)c * N + n];
        bf16 hi  = __float2bfloat16(w);
        res = (s == 1) ? __float2bfloat16(w - __bfloat162float(hi)) : hi;
    }
    out[idx] = res;
}

// ---------------- mma.sync GEMM: out = relu(A @ W + bias) -------------------
// A given as (a_hi, a_lo) bf16, K-extended segments [hi, hi, lo]; W' arranged
// [N][3*lda] bf16 (segments hi, lo, hi). Block tile: 128 x BN, BK = 64.
// Warp grid 2 x (BN/32), warp tile 64 x 32, m16n8k16 HMMA.
// 4-stage cp.async pipeline, ONE __syncthreads per chunk.
template<int BN, bool SPLIT_OUT>
__global__ __launch_bounds__(64 * (BN / 32))
void gemm_mma(const bf16* __restrict__ a_hi, const bf16* __restrict__ a_lo, const int lda,
              const bf16* __restrict__ wt,  const int ldw,
              const float* __restrict__ bias,
              bf16* __restrict__ out_hi, bf16* __restrict__ out_lo,
              float* __restrict__ out_f32, const int ldo)
{
    constexpr int WN      = BN / 32;
    constexpr int THREADS = 64 * WN;
    constexpr int ROWB    = 144;               // padded smem row stride (bytes), BK=64
    constexpr int A_BYTES = 128 * ROWB;
    constexpr int B_BYTES = BN * ROWB;
    constexpr int STAGE   = A_BYTES + B_BYTES;
    constexpr int RPP     = THREADS / 8;       // rows per load pass
    constexpr int A_IT    = 128 / RPP;
    constexpr int B_IT    = BN / RPP;

    extern __shared__ unsigned char smem[];
    const uint32_t sbase = smem_to_u32(smem);

    const int tid  = threadIdx.x;
    const int wid  = tid >> 5;
    const int lid  = tid & 31;
    const int wm   = wid / WN;                 // 0..1
    const int wn   = wid % WN;                 // 0..WN-1

    const int mrow0 = blockIdx.y * 128;
    const int nb0   = blockIdx.x * BN;
    const int nchunks = (3 * lda) / 64;

    // per-thread gmem/smem mapping for tile loads: row = tid/8, 16B-chunk = tid%8
    const int a_r  = tid >> 3, a_c = tid & 7;
    const uint32_t sm_off = (uint32_t)a_r * ROWB + (uint32_t)a_c * 16;
    const bf16* wrow = wt + (size_t)(nb0 + a_r) * ldw + a_c * 8;

    auto issue_tile = [&](int c, int buf) {
        const int kc  = c * 64;
        const int s   = kc / lda;
        const int col = kc - s * lda;
        const bf16* asrc = (s == 2 ? a_lo : a_hi) + (size_t)mrow0 * lda + col + a_c * 8;
        uint32_t As = sbase + buf * STAGE;
        #pragma unroll
        for (int i = 0; i < A_IT; i++)
            cp_async16(As + sm_off + i * RPP * ROWB,
                       asrc + (size_t)(a_r + i * RPP) * lda);
        uint32_t Bs = sbase + buf * STAGE + A_BYTES;
        #pragma unroll
        for (int i = 0; i < B_IT; i++)
            cp_async16(Bs + sm_off + i * RPP * ROWB,
                       wrow + (size_t)i * RPP * ldw + kc);
        cp_commit();
    };

    float acc[4][4][4];
    #pragma unroll
    for (int i = 0; i < 4; i++)
        #pragma unroll
        for (int j = 0; j < 4; j++)
            #pragma unroll
            for (int k = 0; k < 4; k++) acc[i][j][k] = 0.0f;

    // prologue: stages 0,1,2
    issue_tile(0, 0);
    issue_tile(1, 1);
    issue_tile(2, 2);

    // lane bases for ldmatrix (row = .. + (lid&15), 16B half = lid>>4)
    const uint32_t a_lane = (uint32_t)(wm * 64 + (lid & 15)) * ROWB + (uint32_t)(lid >> 4) * 16;
    const uint32_t b_lane = (uint32_t)(wn * 32 + (lid & 15)) * ROWB + (uint32_t)(lid >> 4) * 16;

    for (int c = 0; c < nchunks; c++) {
        const int buf = c & 3;
        cp_wait<2>();
        __syncthreads();
        if (c + 3 < nchunks) issue_tile(c + 3, (c + 3) & 3);
        else cp_commit();                       // keep group count in lockstep

        const uint32_t As = sbase + buf * STAGE + a_lane;
        const uint32_t Bs = sbase + buf * STAGE + A_BYTES + b_lane;

        #pragma unroll
        for (int ks = 0; ks < 4; ks++) {
            uint32_t af[4][4];
            #pragma unroll
            for (int mi = 0; mi < 4; mi++)
                ldsm_x4(af[mi][0], af[mi][1], af[mi][2], af[mi][3],
                        As + mi * 16 * ROWB + ks * 32);
            uint32_t bf_[4][2];
            #pragma unroll
            for (int j = 0; j < 2; j++) {
                uint32_t r0, r1, r2, r3;
                ldsm_x4(r0, r1, r2, r3, Bs + j * 16 * ROWB + ks * 32);
                bf_[j * 2 + 0][0] = r0; bf_[j * 2 + 0][1] = r2;
                bf_[j * 2 + 1][0] = r1; bf_[j * 2 + 1][1] = r3;
            }
            #pragma unroll
            for (int mi = 0; mi < 4; mi++)
                #pragma unroll
                for (int ni = 0; ni < 4; ni++)
                    mma16816(acc[mi][ni], af[mi], bf_[ni]);
        }
    }

    // epilogue: bias + relu from fragments, direct global stores
    #pragma unroll
    for (int mi = 0; mi < 4; mi++) {
        #pragma unroll
        for (int ni = 0; ni < 4; ni++) {
            const int m0 = mrow0 + wm * 64 + mi * 16 + (lid >> 2);
            const int n0 = nb0 + wn * 32 + ni * 8 + (lid & 3) * 2;
            const float b0 = __ldg(&bias[n0]);
            const float b1 = __ldg(&bias[n0 + 1]);
            float v00 = fmaxf(acc[mi][ni][0] + b0, 0.0f);
            float v01 = fmaxf(acc[mi][ni][1] + b1, 0.0f);
            float v10 = fmaxf(acc[mi][ni][2] + b0, 0.0f);
            float v11 = fmaxf(acc[mi][ni][3] + b1, 0.0f);
            if (SPLIT_OUT) {
                bf16 h00 = __float2bfloat16(v00), h01 = __float2bfloat16(v01);
                bf16 h10 = __float2bfloat16(v10), h11 = __float2bfloat16(v11);
                __nv_bfloat162 hp0; hp0.x = h00; hp0.y = h01;
                __nv_bfloat162 hp1; hp1.x = h10; hp1.y = h11;
                __nv_bfloat162 lp0;
                lp0.x = __float2bfloat16(v00 - __bfloat162float(h00));
                lp0.y = __float2bfloat16(v01 - __bfloat162float(h01));
                __nv_bfloat162 lp1;
                lp1.x = __float2bfloat16(v10 - __bfloat162float(h10));
                lp1.y = __float2bfloat16(v11 - __bfloat162float(h11));
                *reinterpret_cast<__nv_bfloat162*>(out_hi + (size_t)m0 * ldo + n0) = hp0;
                *reinterpret_cast<__nv_bfloat162*>(out_hi + (size_t)(m0 + 8) * ldo + n0) = hp1;
                *reinterpret_cast<__nv_bfloat162*>(out_lo + (size_t)m0 * ldo + n0) = lp0;
                *reinterpret_cast<__nv_bfloat162*>(out_lo + (size_t)(m0 + 8) * ldo + n0) = lp1;
            } else {
                *reinterpret_cast<float2*>(out_f32 + (size_t)m0 * ldo + n0) =
                    make_float2(v00, v01);
                *reinterpret_cast<float2*>(out_f32 + (size_t)(m0 + 8) * ldo + n0) =
                    make_float2(v10, v11);
            }
        }
    }
}

// ---------------- head: two 66-dim dots per row ----------------
__global__ void head_kernel(const float* __restrict__ h3,
                            const float* __restrict__ lin,
                            const float* __restrict__ fm,
                            const float* __restrict__ Wc, const float* __restrict__ bc,
                            const float* __restrict__ Wo, const float* __restrict__ bo,
                            float* __restrict__ out)
{
    int gw   = (blockIdx.x * blockDim.x + threadIdx.x) >> 5;
    int lane = threadIdx.x & 31;
    if (gw >= B_ROWS) return;
    const int b = gw;

    float h0 = h3[(size_t)b * H3 + lane];
    float h1v = h3[(size_t)b * H3 + 32 + lane];

    float dc = h0 * Wc[lane] + h1v * Wc[32 + lane];
    float dw = h0 * Wo[lane] + h1v * Wo[32 + lane];
    dc = warp_sum(dc);
    dw = warp_sum(dw);

    if (lane == 0) {
        float l = lin[b], f = fm[b];
        out[b]          = dc + l * Wc[64] + f * Wc[65] + bc[0];
        out[B_ROWS + b] = dw + l * Wo[64] + f * Wo[65] + bo[0];
    }
}

// ---------------- launch ----------------
extern "C" void kernel_launch(void* const* d_in, const int* in_sizes, int n_in,
                              void* d_out, int out_size)
{
    const int*   x_cat    = (const int*)  d_in[0];
    const float* x_num    = (const float*)d_in[1];
    const float* emb0     = (const float*)d_in[2];
    const float* emb1     = (const float*)d_in[3];
    const float* num_bias = (const float*)d_in[4];
    const float* num_emb  = (const float*)d_in[5];
    const float* W1 = (const float*)d_in[6];
    const float* b1 = (const float*)d_in[7];
    const float* W2 = (const float*)d_in[8];
    const float* b2 = (const float*)d_in[9];
    const float* W3 = (const float*)d_in[10];
    const float* b3 = (const float*)d_in[11];
    const float* Wc = (const float*)d_in[12];
    const float* bc = (const float*)d_in[13];
    const float* Wo = (const float*)d_in[14];
    const float* bo = (const float*)d_in[15];
    float* out = (float*)d_out;

    unsigned char* base = nullptr;
    cudaGetSymbolAddress((void**)&base, g_scratch);
    bf16*  e_hi = (bf16*)(base + OFF_EHI);
    bf16*  e_lo = (bf16*)(base + OFF_ELO);
    bf16*  w1t  = (bf16*)(base + OFF_W1T);
    bf16*  w2t  = (bf16*)(base + OFF_W2T);
    bf16*  w3t  = (bf16*)(base + OFF_W3T);
    bf16*  h1h  = (bf16*)(base + OFF_H1H);
    bf16*  h1l  = (bf16*)(base + OFF_H1L);
    bf16*  h2h  = (bf16*)(base + OFF_H2H);
    bf16*  h2l  = (bf16*)(base + OFF_H2L);
    float* h3   = (float*)(base + OFF_H3);
    float* lin  = (float*)(base + OFF_LIN);
    float* fm   = (float*)(base + OFF_FM);

    // smem: 4 stages of (A 128*144 + B BN*144)
    constexpr int SMEM_256 = 4 * (128 * 144 + 256 * 144);  // 221184
    constexpr int SMEM_128 = 4 * (128 * 144 + 128 * 144);  // 147456
    constexpr int SMEM_64  = 4 * (128 * 144 + 64 * 144);   // 110592
    cudaFuncSetAttribute(gemm_mma<256, true>,
                         cudaFuncAttributeMaxDynamicSharedMemorySize, SMEM_256);
    cudaFuncSetAttribute(gemm_mma<128, true>,
                         cudaFuncAttributeMaxDynamicSharedMemorySize, SMEM_128);
    cudaFuncSetAttribute(gemm_mma<64, false>,
                         cudaFuncAttributeMaxDynamicSharedMemorySize, SMEM_64);

    // 0) weight prep (3-segment transposed bf16 splits)
    prep_wt<<<(H1 * 3 * K1P + 255) / 256, 256>>>(W1, w1t, K1, H1, K1P);
    prep_wt<<<(H2 * 3 * H1  + 255) / 256, 256>>>(W2, w2t, H1, H2, H1);
    prep_wt<<<(H3 * 3 * H2  + 255) / 256, 256>>>(W3, w3t, H2, H3, H2);

    // 1) embedding gather + FM/linear (bf16 hi/lo output)
    embed_kernel<<<B_ROWS / 8, 256>>>(x_cat, x_num, emb0, emb1, num_bias,
                                      num_emb, e_hi, e_lo, lin, fm);

    // 2) h1 = relu(e @ W1 + b1)   K' = 3840, full N in one pass
    gemm_mma<256, true><<<dim3(1, B_ROWS / 128), 512, SMEM_256>>>(
        e_hi, e_lo, K1P, w1t, 3 * K1P, b1, h1h, h1l, nullptr, H1);

    // 3) h2 = relu(h1 @ W2 + b2)  K' = 768
    gemm_mma<128, true><<<dim3(1, B_ROWS / 128), 256, SMEM_128>>>(
        h1h, h1l, H1, w2t, 3 * H1, b2, h2h, h2l, nullptr, H2);

    // 4) h3 = relu(h2 @ W3 + b3)  K' = 384, fp32 out
    gemm_mma<64, false><<<dim3(1, B_ROWS / 128), 128, SMEM_64>>>(
        h2h, h2l, H2, w3t, 3 * H2, b3, nullptr, nullptr, h3, H3);

    // 5) head
    head_kernel<<<B_ROWS / 8, 256>>>(h3, lin, fm, Wc, bc, Wo, bo, out);
}

// round 5
// speedup vs baseline: 2.5238x; 1.4663x over previous
#include <cuda_runtime.h>
#include <cuda_fp16.h>
#include <cstdint>
#include <cstddef>

// ---------------- problem constants ----------------
#define B_ROWS 16384
#define F_CAT  26
#define N_NUM  13
#define VOCAB  100000
#define K1     1248
#define K1P    1280   // padded to multiple of 64
#define H1     256
#define H2     128
#define H3     64

// ---------------- scratch (static device memory) ----------------
constexpr size_t ALN(size_t x) { return (x + 255) & ~(size_t)255; }
constexpr size_t OFF_EHI = 0;
constexpr size_t SZ_E    = (size_t)B_ROWS * K1P * 2;              // fp16
constexpr size_t OFF_ELO = ALN(OFF_EHI + SZ_E);
constexpr size_t OFF_W1T = ALN(OFF_ELO + SZ_E);                   // [256][1280] fp16
constexpr size_t OFF_W2T = ALN(OFF_W1T + (size_t)H1 * K1P * 2);   // [128][256]
constexpr size_t OFF_W3T = ALN(OFF_W2T + (size_t)H2 * H1 * 2);    // [64][128]
constexpr size_t OFF_H1H = ALN(OFF_W3T + (size_t)H3 * H2 * 2);
constexpr size_t OFF_H1L = ALN(OFF_H1H + (size_t)B_ROWS * H1 * 2);
constexpr size_t OFF_H2H = ALN(OFF_H1L + (size_t)B_ROWS * H1 * 2);
constexpr size_t OFF_H2L = ALN(OFF_H2H + (size_t)B_ROWS * H2 * 2);
constexpr size_t OFF_H3  = ALN(OFF_H2L + (size_t)B_ROWS * H2 * 2);
constexpr size_t OFF_LIN = ALN(OFF_H3  + (size_t)B_ROWS * H3 * 4);
constexpr size_t OFF_FM  = ALN(OFF_LIN + (size_t)B_ROWS * 4);
constexpr size_t TOTAL_SCRATCH = ALN(OFF_FM + (size_t)B_ROWS * 4);

__device__ __align__(256) unsigned char g_scratch[TOTAL_SCRATCH];

// ---------------- PTX helpers (sm_80-compatible; no 'a' features) ----------
__device__ __forceinline__ uint32_t smem_to_u32(const void* p) {
    uint32_t a;
    asm("{ .reg .u64 t; cvta.to.shared.u64 t, %1; cvt.u32.u64 %0, t; }" : "=r"(a) : "l"(p));
    return a;
}

__device__ __forceinline__ void cp_async16(uint32_t saddr, const void* gaddr) {
    asm volatile("cp.async.cg.shared.global [%0], [%1], 16;"
                 :: "r"(saddr), "l"(gaddr) : "memory");
}
__device__ __forceinline__ void cp_commit() {
    asm volatile("cp.async.commit_group;" ::: "memory");
}
template<int N>
__device__ __forceinline__ void cp_wait() {
    asm volatile("cp.async.wait_group %0;" :: "n"(N) : "memory");
}

__device__ __forceinline__ void ldsm_x4(uint32_t& r0, uint32_t& r1,
                                        uint32_t& r2, uint32_t& r3, uint32_t addr) {
    asm volatile("ldmatrix.sync.aligned.m8n8.x4.shared.b16 {%0,%1,%2,%3}, [%4];"
                 : "=r"(r0), "=r"(r1), "=r"(r2), "=r"(r3) : "r"(addr));
}

// D = A*B + D ; m16n8k16, fp16 in, f32 accum
__device__ __forceinline__ void mma16816(float* d, const uint32_t* a, const uint32_t* b) {
    asm volatile(
        "mma.sync.aligned.m16n8k16.row.col.f32.f16.f16.f32 "
        "{%0,%1,%2,%3}, {%4,%5,%6,%7}, {%8,%9}, {%0,%1,%2,%3};"
        : "+f"(d[0]), "+f"(d[1]), "+f"(d[2]), "+f"(d[3])
        : "r"(a[0]), "r"(a[1]), "r"(a[2]), "r"(a[3]), "r"(b[0]), "r"(b[1]));
}

// ---------------- warp reduce ----------------
__device__ __forceinline__ float warp_sum(float v) {
    #pragma unroll
    for (int o = 16; o > 0; o >>= 1) v += __shfl_down_sync(0xffffffffu, v, o);
    return v;
}

// ---------------- kernel 1: embedding gather + FM + linear (fp16 hi/lo out) --
__global__ void embed_kernel(const int*   __restrict__ x_cat,
                             const float* __restrict__ x_num,
                             const float* __restrict__ emb0,
                             const float* __restrict__ emb1,
                             const float* __restrict__ num_bias,
                             const float* __restrict__ num_emb,
                             __half* __restrict__ e_hi,   // [B, K1P]
                             __half* __restrict__ e_lo,   // [B, K1P]
                             float* __restrict__ lin_out,
                             float* __restrict__ fm_out)
{
    int gw   = (blockIdx.x * blockDim.x + threadIdx.x) >> 5;
    int lane = threadIdx.x & 31;
    if (gw >= B_ROWS) return;
    const int b = gw;

    int   myid = (lane < F_CAT) ? x_cat[(size_t)b * F_CAT + lane] : 0;
    float myx  = (lane < N_NUM) ? x_num[(size_t)b * N_NUM + lane] : 0.0f;

    __half* hrow = e_hi + (size_t)b * K1P;
    __half* lrow = e_lo + (size_t)b * K1P;

    float sum_d = 0.0f, sq_d = 0.0f, lin_p = 0.0f;
    if (lane < F_CAT) lin_p += emb0[(size_t)lane * VOCAB + myid];
    if (lane < N_NUM) lin_p += myx * num_bias[lane];

    #pragma unroll
    for (int f = 0; f < F_CAT; f++) {
        int id  = __shfl_sync(0xffffffffu, myid, f);
        float v = emb1[((size_t)f * VOCAB + id) * 32 + lane];
        sum_d += v; sq_d += v * v;
        __half h = __float2half(v);
        hrow[f * 32 + lane] = h;
        lrow[f * 32 + lane] = __float2half(v - __half2float(h));
    }
    #pragma unroll
    for (int n = 0; n < N_NUM; n++) {
        float xv = __shfl_sync(0xffffffffu, myx, n);
        float v  = xv * num_emb[n * 32 + lane];
        sum_d += v; sq_d += v * v;
        __half h = __float2half(v);
        hrow[(F_CAT + n) * 32 + lane] = h;
        lrow[(F_CAT + n) * 32 + lane] = __float2half(v - __half2float(h));
    }
    __half z = __float2half(0.0f);
    hrow[K1 + lane] = z;
    lrow[K1 + lane] = z;

    float fm  = 0.5f * warp_sum(sum_d * sum_d - sq_d);
    float lin = warp_sum(lin_p);
    if (lane == 0) { lin_out[b] = lin; fm_out[b] = fm; }
}

// ---------------- prep: W' = transposed fp16 (hi only) ----------
// out[n][c] = fp16(W[c][n]), zero-padded for c >= K
__global__ void prep_wt(const float* __restrict__ W, __half* __restrict__ out,
                        int K, int N, int ldw)
{
    int idx = blockIdx.x * blockDim.x + threadIdx.x;
    int tot = N * ldw;
    if (idx >= tot) return;
    int n = idx / ldw;
    int c = idx % ldw;
    out[idx] = (c < K) ? __float2half(W[(size_t)c * N + n]) : __float2half(0.0f);
}

// ---------------- mma.sync GEMM: out = relu(A @ W + bias) -------------------
// A given as (a_hi, a_lo) fp16 2-segment split; W' fp16-hi, [N][ldw] row-major
// (so B is K-major per output, i.e. col-major for the MMA). Per K-chunk of 64,
// ONE B tile is loaded and both A segments run against it.
// Block tile: 128 x BN, BK = 64. Warp grid 2 x (BN/32), warp tile 64 x 32.
// 3-stage cp.async pipeline, one __syncthreads per chunk.
template<int BN, bool SPLIT_OUT>
__global__ __launch_bounds__(64 * (BN / 32))
void gemm_mma(const __half* __restrict__ a_hi, const __half* __restrict__ a_lo,
              const int lda,
              const __half* __restrict__ wt,  const int ldw,
              const float* __restrict__ bias,
              __half* __restrict__ out_hi, __half* __restrict__ out_lo,
              float* __restrict__ out_f32, const int ldo)
{
    constexpr int WN      = BN / 32;
    constexpr int THREADS = 64 * WN;
    constexpr int ROWB    = 144;               // padded smem row stride (bytes)
    constexpr int A_BYTES = 128 * ROWB;        // one segment
    constexpr int B_BYTES = BN * ROWB;
    constexpr int STAGE   = 2 * A_BYTES + B_BYTES;
    constexpr int RPP     = THREADS / 8;       // rows per load pass
    constexpr int A_IT    = 128 / RPP;
    constexpr int B_IT    = BN / RPP;

    extern __shared__ unsigned char smem[];
    const uint32_t sbase = smem_to_u32(smem);

    const int tid  = threadIdx.x;
    const int wid  = tid >> 5;
    const int lid  = tid & 31;
    const int wm   = wid / WN;                 // 0..1
    const int wn   = wid % WN;                 // 0..WN-1

    const int mrow0 = blockIdx.y * 128;
    const int nb0   = blockIdx.x * BN;
    const int nchunks = lda / 64;

    // per-thread gmem/smem mapping for tile loads: row = tid/8, 16B-chunk = tid%8
    const int a_r  = tid >> 3, a_c = tid & 7;
    const uint32_t sm_off = (uint32_t)a_r * ROWB + (uint32_t)a_c * 16;
    const __half* wrow = wt + (size_t)(nb0 + a_r) * ldw + a_c * 8;

    auto issue_tile = [&](int c, int buf) {
        const int kc = c * 64;
        const __half* ah = a_hi + (size_t)mrow0 * lda + kc + a_c * 8;
        const __half* al = a_lo + (size_t)mrow0 * lda + kc + a_c * 8;
        uint32_t As0 = sbase + buf * STAGE;
        uint32_t As1 = As0 + A_BYTES;
        #pragma unroll
        for (int i = 0; i < A_IT; i++)
            cp_async16(As0 + sm_off + i * RPP * ROWB,
                       ah + (size_t)(a_r + i * RPP) * lda);
        #pragma unroll
        for (int i = 0; i < A_IT; i++)
            cp_async16(As1 + sm_off + i * RPP * ROWB,
                       al + (size_t)(a_r + i * RPP) * lda);
        uint32_t Bs = As0 + 2 * A_BYTES;
        #pragma unroll
        for (int i = 0; i < B_IT; i++)
            cp_async16(Bs + sm_off + i * RPP * ROWB,
                       wrow + (size_t)i * RPP * ldw + kc);
        cp_commit();
    };

    float acc[4][4][4];
    #pragma unroll
    for (int i = 0; i < 4; i++)
        #pragma unroll
        for (int j = 0; j < 4; j++)
            #pragma unroll
            for (int k = 0; k < 4; k++) acc[i][j][k] = 0.0f;

    // prologue: stages 0,1  (nchunks >= 2 for all layers)
    issue_tile(0, 0);
    issue_tile(1, 1);

    // lane bases for ldmatrix (row = .. + (lid&15), 16B half = lid>>4)
    const uint32_t a_lane = (uint32_t)(wm * 64 + (lid & 15)) * ROWB + (uint32_t)(lid >> 4) * 16;
    const uint32_t b_lane = (uint32_t)(wn * 32 + (lid & 15)) * ROWB + (uint32_t)(lid >> 4) * 16;

    for (int c = 0; c < nchunks; c++) {
        const int buf = c % 3;
        cp_wait<1>();
        __syncthreads();
        if (c + 2 < nchunks) issue_tile(c + 2, (c + 2) % 3);
        else cp_commit();                       // keep group count in lockstep

        const uint32_t As0 = sbase + buf * STAGE + a_lane;
        const uint32_t Bs  = sbase + buf * STAGE + 2 * A_BYTES + b_lane;

        #pragma unroll
        for (int kk = 0; kk < 4; kk++) {
            // B fragments: loaded once, shared by both A segments
            uint32_t bf_[4][2];
            #pragma unroll
            for (int j = 0; j < 2; j++) {
                uint32_t r0, r1, r2, r3;
                ldsm_x4(r0, r1, r2, r3, Bs + j * 16 * ROWB + kk * 32);
                bf_[j * 2 + 0][0] = r0; bf_[j * 2 + 0][1] = r2;
                bf_[j * 2 + 1][0] = r1; bf_[j * 2 + 1][1] = r3;
            }
            #pragma unroll
            for (int seg = 0; seg < 2; seg++) {
                const uint32_t Abase = As0 + seg * A_BYTES + kk * 32;
                uint32_t af[4][4];
                #pragma unroll
                for (int mi = 0; mi < 4; mi++)
                    ldsm_x4(af[mi][0], af[mi][1], af[mi][2], af[mi][3],
                            Abase + mi * 16 * ROWB);
                #pragma unroll
                for (int mi = 0; mi < 4; mi++)
                    #pragma unroll
                    for (int ni = 0; ni < 4; ni++)
                        mma16816(acc[mi][ni], af[mi], bf_[ni]);
            }
        }
    }

    // epilogue: bias + relu from fragments, direct global stores
    #pragma unroll
    for (int mi = 0; mi < 4; mi++) {
        #pragma unroll
        for (int ni = 0; ni < 4; ni++) {
            const int m0 = mrow0 + wm * 64 + mi * 16 + (lid >> 2);
            const int n0 = nb0 + wn * 32 + ni * 8 + (lid & 3) * 2;
            const float b0 = __ldg(&bias[n0]);
            const float b1 = __ldg(&bias[n0 + 1]);
            float v00 = fmaxf(acc[mi][ni][0] + b0, 0.0f);
            float v01 = fmaxf(acc[mi][ni][1] + b1, 0.0f);
            float v10 = fmaxf(acc[mi][ni][2] + b0, 0.0f);
            float v11 = fmaxf(acc[mi][ni][3] + b1, 0.0f);
            if (SPLIT_OUT) {
                __half h00 = __float2half(v00), h01 = __float2half(v01);
                __half h10 = __float2half(v10), h11 = __float2half(v11);
                __half2 hp0; hp0.x = h00; hp0.y = h01;
                __half2 hp1; hp1.x = h10; hp1.y = h11;
                __half2 lp0;
                lp0.x = __float2half(v00 - __half2float(h00));
                lp0.y = __float2half(v01 - __half2float(h01));
                __half2 lp1;
                lp1.x = __float2half(v10 - __half2float(h10));
                lp1.y = __float2half(v11 - __half2float(h11));
                *reinterpret_cast<__half2*>(out_hi + (size_t)m0 * ldo + n0) = hp0;
                *reinterpret_cast<__half2*>(out_hi + (size_t)(m0 + 8) * ldo + n0) = hp1;
                *reinterpret_cast<__half2*>(out_lo + (size_t)m0 * ldo + n0) = lp0;
                *reinterpret_cast<__half2*>(out_lo + (size_t)(m0 + 8) * ldo + n0) = lp1;
            } else {
                *reinterpret_cast<float2*>(out_f32 + (size_t)m0 * ldo + n0) =
                    make_float2(v00, v01);
                *reinterpret_cast<float2*>(out_f32 + (size_t)(m0 + 8) * ldo + n0) =
                    make_float2(v10, v11);
            }
        }
    }
}

// ---------------- head: two 66-dim dots per row ----------------
__global__ void head_kernel(const float* __restrict__ h3,
                            const float* __restrict__ lin,
                            const float* __restrict__ fm,
                            const float* __restrict__ Wc, const float* __restrict__ bc,
                            const float* __restrict__ Wo, const float* __restrict__ bo,
                            float* __restrict__ out)
{
    int gw   = (blockIdx.x * blockDim.x + threadIdx.x) >> 5;
    int lane = threadIdx.x & 31;
    if (gw >= B_ROWS) return;
    const int b = gw;

    float h0 = h3[(size_t)b * H3 + lane];
    float h1v = h3[(size_t)b * H3 + 32 + lane];

    float dc = h0 * Wc[lane] + h1v * Wc[32 + lane];
    float dw = h0 * Wo[lane] + h1v * Wo[32 + lane];
    dc = warp_sum(dc);
    dw = warp_sum(dw);

    if (lane == 0) {
        float l = lin[b], f = fm[b];
        out[b]          = dc + l * Wc[64] + f * Wc[65] + bc[0];
        out[B_ROWS + b] = dw + l * Wo[64] + f * Wo[65] + bo[0];
    }
}

// ---------------- launch ----------------
extern "C" void kernel_launch(void* const* d_in, const int* in_sizes, int n_in,
                              void* d_out, int out_size)
{
    const int*   x_cat    = (const int*)  d_in[0];
    const float* x_num    = (const float*)d_in[1];
    const float* emb0     = (const float*)d_in[2];
    const float* emb1     = (const float*)d_in[3];
    const float* num_bias = (const float*)d_in[4];
    const float* num_emb  = (const float*)d_in[5];
    const float* W1 = (const float*)d_in[6];
    const float* b1 = (const float*)d_in[7];
    const float* W2 = (const float*)d_in[8];
    const float* b2 = (const float*)d_in[9];
    const float* W3 = (const float*)d_in[10];
    const float* b3 = (const float*)d_in[11];
    const float* Wc = (const float*)d_in[12];
    const float* bc = (const float*)d_in[13];
    const float* Wo = (const float*)d_in[14];
    const float* bo = (const float*)d_in[15];
    float* out = (float*)d_out;

    unsigned char* base = nullptr;
    cudaGetSymbolAddress((void**)&base, g_scratch);
    __half* e_hi = (__half*)(base + OFF_EHI);
    __half* e_lo = (__half*)(base + OFF_ELO);
    __half* w1t  = (__half*)(base + OFF_W1T);
    __half* w2t  = (__half*)(base + OFF_W2T);
    __half* w3t  = (__half*)(base + OFF_W3T);
    __half* h1h  = (__half*)(base + OFF_H1H);
    __half* h1l  = (__half*)(base + OFF_H1L);
    __half* h2h  = (__half*)(base + OFF_H2H);
    __half* h2l  = (__half*)(base + OFF_H2L);
    float*  h3   = (float*)(base + OFF_H3);
    float*  lin  = (float*)(base + OFF_LIN);
    float*  fm   = (float*)(base + OFF_FM);

    // smem: 3 stages of (2*A 128*144 + B BN*144)
    constexpr int SMEM_256 = 3 * (2 * 128 * 144 + 256 * 144);  // 221184
    constexpr int SMEM_128 = 3 * (2 * 128 * 144 + 128 * 144);  // 165888
    constexpr int SMEM_64  = 3 * (2 * 128 * 144 + 64 * 144);   // 138240
    cudaFuncSetAttribute(gemm_mma<256, true>,
                         cudaFuncAttributeMaxDynamicSharedMemorySize, SMEM_256);
    cudaFuncSetAttribute(gemm_mma<128, true>,
                         cudaFuncAttributeMaxDynamicSharedMemorySize, SMEM_128);
    cudaFuncSetAttribute(gemm_mma<64, false>,
                         cudaFuncAttributeMaxDynamicSharedMemorySize, SMEM_64);

    // 0) weight prep (transposed fp16-hi)
    prep_wt<<<(H1 * K1P + 255) / 256, 256>>>(W1, w1t, K1, H1, K1P);
    prep_wt<<<(H2 * H1  + 255) / 256, 256>>>(W2, w2t, H1, H2, H1);
    prep_wt<<<(H3 * H2  + 255) / 256, 256>>>(W3, w3t, H2, H3, H2);

    // 1) embedding gather + FM/linear (fp16 hi/lo output)
    embed_kernel<<<B_ROWS / 8, 256>>>(x_cat, x_num, emb0, emb1, num_bias,
                                      num_emb, e_hi, e_lo, lin, fm);

    // 2) h1 = relu(e @ W1 + b1)   K = 1280, 2-segment fp16
    gemm_mma<256, true><<<dim3(1, B_ROWS / 128), 512, SMEM_256>>>(
        e_hi, e_lo, K1P, w1t, K1P, b1, h1h, h1l, nullptr, H1);

    // 3) h2 = relu(h1 @ W2 + b2)  K = 256
    gemm_mma<128, true><<<dim3(1, B_ROWS / 128), 256, SMEM_128>>>(
        h1h, h1l, H1, w2t, H1, b2, h2h, h2l, nullptr, H2);

    // 4) h3 = relu(h2 @ W3 + b3)  K = 128, fp32 out
    gemm_mma<64, false><<<dim3(1, B_ROWS / 128), 128, SMEM_64>>>(
        h2h, h2l, H2, w3t, H2, b3, nullptr, nullptr, h3, H3);

    // 5) head
    head_kernel<<<B_ROWS / 8, 256>>>(h3, lin, fm, Wc, bc, Wo, bo, out);
}

// round 6
// speedup vs baseline: 3.8409x; 1.5219x over previous
#include <cuda_runtime.h>
#include <cuda_fp16.h>
#include <cstdint>
#include <cstddef>

// ---------------- problem constants ----------------
#define B_ROWS 16384
#define F_CAT  26
#define N_NUM  13
#define VOCAB  100000
#define K1     1248
#define K1P    1280   // padded to multiple of 64
#define H1     256
#define H2     128
#define H3     64

// ---------------- scratch (static device memory) ----------------
constexpr size_t ALN(size_t x) { return (x + 255) & ~(size_t)255; }
constexpr size_t OFF_E   = 0;                                     // fp16 [B][K1P]
constexpr size_t OFF_W1T = ALN(OFF_E   + (size_t)B_ROWS * K1P * 2);
constexpr size_t OFF_W2T = ALN(OFF_W1T + (size_t)H1 * K1P * 2);   // [128][256]
constexpr size_t OFF_W3T = ALN(OFF_W2T + (size_t)H2 * H1 * 2);    // [64][128]
constexpr size_t OFF_H1  = ALN(OFF_W3T + (size_t)H3 * H2 * 2);    // fp16 [B][256]
constexpr size_t OFF_H2  = ALN(OFF_H1  + (size_t)B_ROWS * H1 * 2);
constexpr size_t OFF_H3  = ALN(OFF_H2  + (size_t)B_ROWS * H2 * 2);// fp32 [B][64]
constexpr size_t OFF_LIN = ALN(OFF_H3  + (size_t)B_ROWS * H3 * 4);
constexpr size_t OFF_FM  = ALN(OFF_LIN + (size_t)B_ROWS * 4);
constexpr size_t TOTAL_SCRATCH = ALN(OFF_FM + (size_t)B_ROWS * 4);

__device__ __align__(256) unsigned char g_scratch[TOTAL_SCRATCH];

// ---------------- PTX helpers (sm_80-compatible; no 'a' features) ----------
__device__ __forceinline__ uint32_t smem_to_u32(const void* p) {
    uint32_t a;
    asm("{ .reg .u64 t; cvta.to.shared.u64 t, %1; cvt.u32.u64 %0, t; }" : "=r"(a) : "l"(p));
    return a;
}

__device__ __forceinline__ void cp_async16(uint32_t saddr, const void* gaddr) {
    asm volatile("cp.async.cg.shared.global [%0], [%1], 16;"
                 :: "r"(saddr), "l"(gaddr) : "memory");
}
__device__ __forceinline__ void cp_commit() {
    asm volatile("cp.async.commit_group;" ::: "memory");
}
template<int N>
__device__ __forceinline__ void cp_wait() {
    asm volatile("cp.async.wait_group %0;" :: "n"(N) : "memory");
}

__device__ __forceinline__ void ldsm_x4(uint32_t& r0, uint32_t& r1,
                                        uint32_t& r2, uint32_t& r3, uint32_t addr) {
    asm volatile("ldmatrix.sync.aligned.m8n8.x4.shared.b16 {%0,%1,%2,%3}, [%4];"
                 : "=r"(r0), "=r"(r1), "=r"(r2), "=r"(r3) : "r"(addr));
}

// D = A*B + D ; m16n8k16, fp16 in, f32 accum
__device__ __forceinline__ void mma16816(float* d, const uint32_t* a, const uint32_t* b) {
    asm volatile(
        "mma.sync.aligned.m16n8k16.row.col.f32.f16.f16.f32 "
        "{%0,%1,%2,%3}, {%4,%5,%6,%7}, {%8,%9}, {%0,%1,%2,%3};"
        : "+f"(d[0]), "+f"(d[1]), "+f"(d[2]), "+f"(d[3])
        : "r"(a[0]), "r"(a[1]), "r"(a[2]), "r"(a[3]), "r"(b[0]), "r"(b[1]));
}

// ---------------- warp reduce ----------------
__device__ __forceinline__ float warp_sum(float v) {
    #pragma unroll
    for (int o = 16; o > 0; o >>= 1) v += __shfl_down_sync(0xffffffffu, v, o);
    return v;
}

// ---------------- kernel 1: embedding gather + FM + linear (fp16 out) -------
__global__ void embed_kernel(const int*   __restrict__ x_cat,
                             const float* __restrict__ x_num,
                             const float* __restrict__ emb0,
                             const float* __restrict__ emb1,
                             const float* __restrict__ num_bias,
                             const float* __restrict__ num_emb,
                             __half* __restrict__ e_out,  // [B, K1P]
                             float* __restrict__ lin_out,
                             float* __restrict__ fm_out)
{
    int gw   = (blockIdx.x * blockDim.x + threadIdx.x) >> 5;
    int lane = threadIdx.x & 31;
    if (gw >= B_ROWS) return;
    const int b = gw;

    int   myid = (lane < F_CAT) ? x_cat[(size_t)b * F_CAT + lane] : 0;
    float myx  = (lane < N_NUM) ? x_num[(size_t)b * N_NUM + lane] : 0.0f;

    __half* erow = e_out + (size_t)b * K1P;

    float sum_d = 0.0f, sq_d = 0.0f, lin_p = 0.0f;
    if (lane < F_CAT) lin_p += emb0[(size_t)lane * VOCAB + myid];
    if (lane < N_NUM) lin_p += myx * num_bias[lane];

    #pragma unroll
    for (int f = 0; f < F_CAT; f++) {
        int id  = __shfl_sync(0xffffffffu, myid, f);
        float v = emb1[((size_t)f * VOCAB + id) * 32 + lane];
        sum_d += v; sq_d += v * v;
        erow[f * 32 + lane] = __float2half(v);
    }
    #pragma unroll
    for (int n = 0; n < N_NUM; n++) {
        float xv = __shfl_sync(0xffffffffu, myx, n);
        float v  = xv * num_emb[n * 32 + lane];
        sum_d += v; sq_d += v * v;
        erow[(F_CAT + n) * 32 + lane] = __float2half(v);
    }
    erow[K1 + lane] = __float2half(0.0f);

    float fm  = 0.5f * warp_sum(sum_d * sum_d - sq_d);
    float lin = warp_sum(lin_p);
    if (lane == 0) { lin_out[b] = lin; fm_out[b] = fm; }
}

// ---------------- prep: W' = transposed fp16 ----------
// out[n][c] = fp16(W[c][n]), zero-padded for c >= K
__global__ void prep_wt(const float* __restrict__ W, __half* __restrict__ out,
                        int K, int N, int ldw)
{
    int idx = blockIdx.x * blockDim.x + threadIdx.x;
    int tot = N * ldw;
    if (idx >= tot) return;
    int n = idx / ldw;
    int c = idx % ldw;
    out[idx] = (c < K) ? __float2half(W[(size_t)c * N + n]) : __float2half(0.0f);
}

// ---------------- mma.sync GEMM: out = relu(A @ W + bias) -------------------
// A fp16 [M][lda] row-major; W' fp16 [N][ldw] row-major (K-major per output,
// i.e. col-major B for the MMA). Block tile: 128 x BN, BK = 64.
// Warp grid 2 x (BN/32), warp tile 64 x 32, m16n8k16 HMMA.
// 3-stage cp.async pipeline, one __syncthreads per chunk.
template<int BN, bool F16_OUT>
__global__ __launch_bounds__(64 * (BN / 32))
void gemm_mma(const __half* __restrict__ A, const int lda,
              const __half* __restrict__ wt, const int ldw,
              const float* __restrict__ bias,
              __half* __restrict__ out_f16,
              float* __restrict__ out_f32, const int ldo)
{
    constexpr int WN      = BN / 32;
    constexpr int THREADS = 64 * WN;
    constexpr int ROWB    = 144;               // padded smem row stride (bytes)
    constexpr int A_BYTES = 128 * ROWB;
    constexpr int B_BYTES = BN * ROWB;
    constexpr int STAGE   = A_BYTES + B_BYTES;
    constexpr int RPP     = THREADS / 8;       // rows per load pass
    constexpr int A_IT    = 128 / RPP;
    constexpr int B_IT    = BN / RPP;

    extern __shared__ unsigned char smem[];
    const uint32_t sbase = smem_to_u32(smem);

    const int tid  = threadIdx.x;
    const int wid  = tid >> 5;
    const int lid  = tid & 31;
    const int wm   = wid / WN;                 // 0..1
    const int wn   = wid % WN;                 // 0..WN-1

    const int mrow0 = blockIdx.y * 128;
    const int nb0   = blockIdx.x * BN;
    const int nchunks = lda / 64;

    // per-thread gmem/smem mapping for tile loads: row = tid/8, 16B-chunk = tid%8
    const int a_r  = tid >> 3, a_c = tid & 7;
    const uint32_t sm_off = (uint32_t)a_r * ROWB + (uint32_t)a_c * 16;
    const __half* arow = A + (size_t)(mrow0 + a_r) * lda + a_c * 8;
    const __half* wrow = wt + (size_t)(nb0 + a_r) * ldw + a_c * 8;

    auto issue_tile = [&](int c, int buf) {
        const int kc = c * 64;
        uint32_t As = sbase + buf * STAGE;
        #pragma unroll
        for (int i = 0; i < A_IT; i++)
            cp_async16(As + sm_off + i * RPP * ROWB,
                       arow + (size_t)i * RPP * lda + kc);
        uint32_t Bs = As + A_BYTES;
        #pragma unroll
        for (int i = 0; i < B_IT; i++)
            cp_async16(Bs + sm_off + i * RPP * ROWB,
                       wrow + (size_t)i * RPP * ldw + kc);
        cp_commit();
    };

    float acc[4][4][4];
    #pragma unroll
    for (int i = 0; i < 4; i++)
        #pragma unroll
        for (int j = 0; j < 4; j++)
            #pragma unroll
            for (int k = 0; k < 4; k++) acc[i][j][k] = 0.0f;

    // prologue: stages 0,1  (nchunks >= 2 for all layers)
    issue_tile(0, 0);
    issue_tile(1, 1);

    // lane bases for ldmatrix (row = .. + (lid&15), 16B half = lid>>4)
    const uint32_t a_lane = (uint32_t)(wm * 64 + (lid & 15)) * ROWB + (uint32_t)(lid >> 4) * 16;
    const uint32_t b_lane = (uint32_t)(wn * 32 + (lid & 15)) * ROWB + (uint32_t)(lid >> 4) * 16;

    for (int c = 0; c < nchunks; c++) {
        const int buf = c % 3;
        cp_wait<1>();
        __syncthreads();
        if (c + 2 < nchunks) issue_tile(c + 2, (c + 2) % 3);
        else cp_commit();                       // keep group count in lockstep

        const uint32_t As = sbase + buf * STAGE + a_lane;
        const uint32_t Bs = sbase + buf * STAGE + A_BYTES + b_lane;

        #pragma unroll
        for (int kk = 0; kk < 4; kk++) {
            uint32_t bf_[4][2];
            #pragma unroll
            for (int j = 0; j < 2; j++) {
                uint32_t r0, r1, r2, r3;
                ldsm_x4(r0, r1, r2, r3, Bs + j * 16 * ROWB + kk * 32);
                bf_[j * 2 + 0][0] = r0; bf_[j * 2 + 0][1] = r2;
                bf_[j * 2 + 1][0] = r1; bf_[j * 2 + 1][1] = r3;
            }
            uint32_t af[4][4];
            #pragma unroll
            for (int mi = 0; mi < 4; mi++)
                ldsm_x4(af[mi][0], af[mi][1], af[mi][2], af[mi][3],
                        As + mi * 16 * ROWB + kk * 32);
            #pragma unroll
            for (int mi = 0; mi < 4; mi++)
                #pragma unroll
                for (int ni = 0; ni < 4; ni++)
                    mma16816(acc[mi][ni], af[mi], bf_[ni]);
        }
    }

    // epilogue: bias + relu from fragments, direct global stores
    #pragma unroll
    for (int mi = 0; mi < 4; mi++) {
        #pragma unroll
        for (int ni = 0; ni < 4; ni++) {
            const int m0 = mrow0 + wm * 64 + mi * 16 + (lid >> 2);
            const int n0 = nb0 + wn * 32 + ni * 8 + (lid & 3) * 2;
            const float b0 = __ldg(&bias[n0]);
            const float b1 = __ldg(&bias[n0 + 1]);
            float v00 = fmaxf(acc[mi][ni][0] + b0, 0.0f);
            float v01 = fmaxf(acc[mi][ni][1] + b1, 0.0f);
            float v10 = fmaxf(acc[mi][ni][2] + b0, 0.0f);
            float v11 = fmaxf(acc[mi][ni][3] + b1, 0.0f);
            if (F16_OUT) {
                __half2 p0; p0.x = __float2half(v00); p0.y = __float2half(v01);
                __half2 p1; p1.x = __float2half(v10); p1.y = __float2half(v11);
                *reinterpret_cast<__half2*>(out_f16 + (size_t)m0 * ldo + n0) = p0;
                *reinterpret_cast<__half2*>(out_f16 + (size_t)(m0 + 8) * ldo + n0) = p1;
            } else {
                *reinterpret_cast<float2*>(out_f32 + (size_t)m0 * ldo + n0) =
                    make_float2(v00, v01);
                *reinterpret_cast<float2*>(out_f32 + (size_t)(m0 + 8) * ldo + n0) =
                    make_float2(v10, v11);
            }
        }
    }
}

// ---------------- head: two 66-dim dots per row ----------------
__global__ void head_kernel(const float* __restrict__ h3,
                            const float* __restrict__ lin,
                            const float* __restrict__ fm,
                            const float* __restrict__ Wc, const float* __restrict__ bc,
                            const float* __restrict__ Wo, const float* __restrict__ bo,
                            float* __restrict__ out)
{
    int gw   = (blockIdx.x * blockDim.x + threadIdx.x) >> 5;
    int lane = threadIdx.x & 31;
    if (gw >= B_ROWS) return;
    const int b = gw;

    float h0 = h3[(size_t)b * H3 + lane];
    float h1v = h3[(size_t)b * H3 + 32 + lane];

    float dc = h0 * Wc[lane] + h1v * Wc[32 + lane];
    float dw = h0 * Wo[lane] + h1v * Wo[32 + lane];
    dc = warp_sum(dc);
    dw = warp_sum(dw);

    if (lane == 0) {
        float l = lin[b], f = fm[b];
        out[b]          = dc + l * Wc[64] + f * Wc[65] + bc[0];
        out[B_ROWS + b] = dw + l * Wo[64] + f * Wo[65] + bo[0];
    }
}

// ---------------- launch ----------------
extern "C" void kernel_launch(void* const* d_in, const int* in_sizes, int n_in,
                              void* d_out, int out_size)
{
    const int*   x_cat    = (const int*)  d_in[0];
    const float* x_num    = (const float*)d_in[1];
    const float* emb0     = (const float*)d_in[2];
    const float* emb1     = (const float*)d_in[3];
    const float* num_bias = (const float*)d_in[4];
    const float* num_emb  = (const float*)d_in[5];
    const float* W1 = (const float*)d_in[6];
    const float* b1 = (const float*)d_in[7];
    const float* W2 = (const float*)d_in[8];
    const float* b2 = (const float*)d_in[9];
    const float* W3 = (const float*)d_in[10];
    const float* b3 = (const float*)d_in[11];
    const float* Wc = (const float*)d_in[12];
    const float* bc = (const float*)d_in[13];
    const float* Wo = (const float*)d_in[14];
    const float* bo = (const float*)d_in[15];
    float* out = (float*)d_out;

    unsigned char* base = nullptr;
    cudaGetSymbolAddress((void**)&base, g_scratch);
    __half* e    = (__half*)(base + OFF_E);
    __half* w1t  = (__half*)(base + OFF_W1T);
    __half* w2t  = (__half*)(base + OFF_W2T);
    __half* w3t  = (__half*)(base + OFF_W3T);
    __half* h1   = (__half*)(base + OFF_H1);
    __half* h2   = (__half*)(base + OFF_H2);
    float*  h3   = (float*)(base + OFF_H3);
    float*  lin  = (float*)(base + OFF_LIN);
    float*  fm   = (float*)(base + OFF_FM);

    // smem: 3 stages of (A 128*144 + B BN*144)
    constexpr int SMEM_256 = 3 * ((128 + 256) * 144);  // 165888
    constexpr int SMEM_128 = 3 * ((128 + 128) * 144);  // 110592
    constexpr int SMEM_64  = 3 * ((128 + 64) * 144);   // 82944
    cudaFuncSetAttribute(gemm_mma<256, true>,
                         cudaFuncAttributeMaxDynamicSharedMemorySize, SMEM_256);
    cudaFuncSetAttribute(gemm_mma<128, true>,
                         cudaFuncAttributeMaxDynamicSharedMemorySize, SMEM_128);
    cudaFuncSetAttribute(gemm_mma<64, false>,
                         cudaFuncAttributeMaxDynamicSharedMemorySize, SMEM_64);

    // 0) weight prep (transposed fp16)
    prep_wt<<<(H1 * K1P + 255) / 256, 256>>>(W1, w1t, K1, H1, K1P);
    prep_wt<<<(H2 * H1  + 255) / 256, 256>>>(W2, w2t, H1, H2, H1);
    prep_wt<<<(H3 * H2  + 255) / 256, 256>>>(W3, w3t, H2, H3, H2);

    // 1) embedding gather + FM/linear (fp16 output)
    embed_kernel<<<B_ROWS / 8, 256>>>(x_cat, x_num, emb0, emb1, num_bias,
                                      num_emb, e, lin, fm);

    // 2) h1 = relu(e @ W1 + b1)   K = 1280
    gemm_mma<256, true><<<dim3(1, B_ROWS / 128), 512, SMEM_256>>>(
        e, K1P, w1t, K1P, b1, h1, nullptr, H1);

    // 3) h2 = relu(h1 @ W2 + b2)  K = 256
    gemm_mma<128, true><<<dim3(1, B_ROWS / 128), 256, SMEM_128>>>(
        h1, H1, w2t, H1, b2, h2, nullptr, H2);

    // 4) h3 = relu(h2 @ W3 + b3)  K = 128, fp32 out
    gemm_mma<64, false><<<dim3(1, B_ROWS / 128), 128, SMEM_64>>>(
        h2, H2, w3t, H2, b3, nullptr, h3, H3);

    // 5) head
    head_kernel<<<B_ROWS / 8, 256>>>(h3, lin, fm, Wc, bc, Wo, bo, out);
}

// round 7
// speedup vs baseline: 4.9249x; 1.2822x over previous
#include <cuda_runtime.h>
#include <cuda_fp16.h>
#include <cstdint>
#include <cstddef>

// ---------------- problem constants ----------------
#define B_ROWS 16384
#define F_CAT  26
#define N_NUM  13
#define VOCAB  100000
#define K1     1248
#define K1P    1280   // padded to multiple of 64
#define H1     256
#define H2     128
#define H3     64

// ---------------- scratch (static device memory) ----------------
constexpr size_t ALN(size_t x) { return (x + 255) & ~(size_t)255; }
constexpr size_t OFF_E   = 0;                                     // fp16 [B][K1P]
constexpr size_t OFF_W1T = ALN(OFF_E   + (size_t)B_ROWS * K1P * 2);
constexpr size_t OFF_W2T = ALN(OFF_W1T + (size_t)H1 * K1P * 2);   // [128][256]
constexpr size_t OFF_W3T = ALN(OFF_W2T + (size_t)H2 * H1 * 2);    // [64][128]
constexpr size_t OFF_LIN = ALN(OFF_W3T + (size_t)H3 * H2 * 2);
constexpr size_t OFF_FM  = ALN(OFF_LIN + (size_t)B_ROWS * 4);
constexpr size_t TOTAL_SCRATCH = ALN(OFF_FM + (size_t)B_ROWS * 4);

__device__ __align__(256) unsigned char g_scratch[TOTAL_SCRATCH];

// ---------------- smem layout for the megakernel (bytes) ----------------
// mainloop: 3 stages x (128+256) rows x 144B = 165888, at offset 0
// afterwards (post-sync reuse):
#define SM_H1   0          // h1 tile  [128][264 halves]  stride 528B
#define SM_W2   69632      // W2' tile [128][264 halves]  stride 528B (K=256)
#define SM_H2   139264     // h2 tile  [128][136 halves]  stride 272B
#define SM_W3   174336     // W3' tile [64][136 halves]   stride 272B (K=128)
#define SM_H3   192000     // h3 tile  [128][68 floats]   stride 272B
#define SM_HEAD 226816     // Wc (66 f32) | Wo (66 f32)
#define SMEM_MEGA 227344

// ---------------- PTX helpers (sm_80-compatible; no 'a' features) ----------
__device__ __forceinline__ uint32_t smem_to_u32(const void* p) {
    uint32_t a;
    asm("{ .reg .u64 t; cvta.to.shared.u64 t, %1; cvt.u32.u64 %0, t; }" : "=r"(a) : "l"(p));
    return a;
}

__device__ __forceinline__ void cp_async16(uint32_t saddr, const void* gaddr) {
    asm volatile("cp.async.cg.shared.global [%0], [%1], 16;"
                 :: "r"(saddr), "l"(gaddr) : "memory");
}
__device__ __forceinline__ void cp_commit() {
    asm volatile("cp.async.commit_group;" ::: "memory");
}
template<int N>
__device__ __forceinline__ void cp_wait() {
    asm volatile("cp.async.wait_group %0;" :: "n"(N) : "memory");
}

__device__ __forceinline__ void ldsm_x4(uint32_t& r0, uint32_t& r1,
                                        uint32_t& r2, uint32_t& r3, uint32_t addr) {
    asm volatile("ldmatrix.sync.aligned.m8n8.x4.shared.b16 {%0,%1,%2,%3}, [%4];"
                 : "=r"(r0), "=r"(r1), "=r"(r2), "=r"(r3) : "r"(addr));
}

// D = A*B + D ; m16n8k16, fp16 in, f32 accum
__device__ __forceinline__ void mma16816(float* d, const uint32_t* a, const uint32_t* b) {
    asm volatile(
        "mma.sync.aligned.m16n8k16.row.col.f32.f16.f16.f32 "
        "{%0,%1,%2,%3}, {%4,%5,%6,%7}, {%8,%9}, {%0,%1,%2,%3};"
        : "+f"(d[0]), "+f"(d[1]), "+f"(d[2]), "+f"(d[3])
        : "r"(a[0]), "r"(a[1]), "r"(a[2]), "r"(a[3]), "r"(b[0]), "r"(b[1]));
}

// ---------------- warp reduce ----------------
__device__ __forceinline__ float warp_sum(float v) {
    #pragma unroll
    for (int o = 16; o > 0; o >>= 1) v += __shfl_down_sync(0xffffffffu, v, o);
    return v;
}

// ---------------- kernel 1: embedding gather + FM + linear (fp16 out) -------
__global__ void embed_kernel(const int*   __restrict__ x_cat,
                             const float* __restrict__ x_num,
                             const float* __restrict__ emb0,
                             const float* __restrict__ emb1,
                             const float* __restrict__ num_bias,
                             const float* __restrict__ num_emb,
                             __half* __restrict__ e_out,  // [B, K1P]
                             float* __restrict__ lin_out,
                             float* __restrict__ fm_out)
{
    int gw   = (blockIdx.x * blockDim.x + threadIdx.x) >> 5;
    int lane = threadIdx.x & 31;
    if (gw >= B_ROWS) return;
    const int b = gw;

    int   myid = (lane < F_CAT) ? x_cat[(size_t)b * F_CAT + lane] : 0;
    float myx  = (lane < N_NUM) ? x_num[(size_t)b * N_NUM + lane] : 0.0f;

    __half* erow = e_out + (size_t)b * K1P;

    float sum_d = 0.0f, sq_d = 0.0f, lin_p = 0.0f;
    if (lane < F_CAT) lin_p += emb0[(size_t)lane * VOCAB + myid];
    if (lane < N_NUM) lin_p += myx * num_bias[lane];

    #pragma unroll
    for (int f = 0; f < F_CAT; f++) {
        int id  = __shfl_sync(0xffffffffu, myid, f);
        float v = emb1[((size_t)f * VOCAB + id) * 32 + lane];
        sum_d += v; sq_d += v * v;
        erow[f * 32 + lane] = __float2half(v);
    }
    #pragma unroll
    for (int n = 0; n < N_NUM; n++) {
        float xv = __shfl_sync(0xffffffffu, myx, n);
        float v  = xv * num_emb[n * 32 + lane];
        sum_d += v; sq_d += v * v;
        erow[(F_CAT + n) * 32 + lane] = __float2half(v);
    }
    erow[K1 + lane] = __float2half(0.0f);

    float fm  = 0.5f * warp_sum(sum_d * sum_d - sq_d);
    float lin = warp_sum(lin_p);
    if (lane == 0) { lin_out[b] = lin; fm_out[b] = fm; }
}

// ---------------- prep: all three transposed fp16 weight tiles ----------
__global__ void prep_all(const float* __restrict__ W1, __half* __restrict__ o1,
                         const float* __restrict__ W2, __half* __restrict__ o2,
                         const float* __restrict__ W3, __half* __restrict__ o3)
{
    int idx = blockIdx.x * blockDim.x + threadIdx.x;
    const int T1 = H1 * K1P;            // 327680
    const int T2 = H2 * H1;             // 32768
    const int T3 = H3 * H2;             // 8192
    if (idx < T1) {
        int n = idx / K1P, c = idx % K1P;
        o1[idx] = (c < K1) ? __float2half(W1[(size_t)c * H1 + n]) : __float2half(0.0f);
    } else if (idx < T1 + T2) {
        int r = idx - T1;
        int n = r / H1, c = r % H1;
        o2[r] = __float2half(W2[(size_t)c * H2 + n]);
    } else if (idx < T1 + T2 + T3) {
        int r = idx - T1 - T2;
        int n = r / H2, c = r % H2;
        o3[r] = __float2half(W3[(size_t)c * H3 + n]);
    }
}

// ---------------- megakernel: full MLP + head per 128-row tile --------------
// stage 1: h1 = relu(e @ W1 + b1)       mainloop over K=1280 (gmem, 3-stage)
// stage 2: h2 = relu(h1 @ W2 + b2)      from smem
// stage 3: h3 = relu(h2 @ W3 + b3)      from smem
// head:    logits from h3 + lin + fm
__global__ __launch_bounds__(512)
void mega_mlp(const __half* __restrict__ A, // e [B][K1P]
              const __half* __restrict__ w1t,
              const __half* __restrict__ w2t,
              const __half* __restrict__ w3t,
              const float* __restrict__ b1,
              const float* __restrict__ b2,
              const float* __restrict__ b3,
              const float* __restrict__ Wc, const float* __restrict__ bc,
              const float* __restrict__ Wo, const float* __restrict__ bo,
              const float* __restrict__ lin, const float* __restrict__ fm,
              float* __restrict__ out)
{
    constexpr int BN      = 256;
    constexpr int WN      = 8;                 // warps along N (stage 1)
    constexpr int THREADS = 512;
    constexpr int ROWB    = 144;
    constexpr int A_BYTES = 128 * ROWB;
    constexpr int B_BYTES = BN * ROWB;
    constexpr int STAGE   = A_BYTES + B_BYTES; // 55296
    constexpr int RPP     = THREADS / 8;       // 64 rows per pass
    constexpr int lda     = K1P;

    extern __shared__ unsigned char smem[];
    const uint32_t sbase = smem_to_u32(smem);

    const int tid = threadIdx.x;
    const int wid = tid >> 5;
    const int lid = tid & 31;

    const int mrow0 = blockIdx.y * 128;

    // ---------------- stage 1 mainloop ----------------
    const int a_r = tid >> 3, a_c = tid & 7;
    const uint32_t sm_off = (uint32_t)a_r * ROWB + (uint32_t)a_c * 16;
    const __half* arow = A + (size_t)(mrow0 + a_r) * lda + a_c * 8;
    const __half* wrow = w1t + (size_t)a_r * lda + a_c * 8;

    auto issue_tile = [&](int c, int buf) {
        const int kc = c * 64;
        uint32_t As = sbase + buf * STAGE;
        #pragma unroll
        for (int i = 0; i < 2; i++)
            cp_async16(As + sm_off + i * RPP * ROWB, arow + (size_t)i * RPP * lda + kc);
        uint32_t Bs = As + A_BYTES;
        #pragma unroll
        for (int i = 0; i < 4; i++)
            cp_async16(Bs + sm_off + i * RPP * ROWB, wrow + (size_t)i * RPP * lda + kc);
        cp_commit();
    };

    float acc[4][4][4];
    #pragma unroll
    for (int i = 0; i < 4; i++)
        #pragma unroll
        for (int j = 0; j < 4; j++)
            #pragma unroll
            for (int k = 0; k < 4; k++) acc[i][j][k] = 0.0f;

    issue_tile(0, 0);
    issue_tile(1, 1);
    issue_tile(2, 2);

    const int wm = wid / WN;                   // 0..1
    const int wn = wid % WN;                   // 0..7
    const uint32_t a_lane = (uint32_t)(wm * 64 + (lid & 15)) * ROWB + (uint32_t)(lid >> 4) * 16;
    const uint32_t b_lane = (uint32_t)(wn * 32 + (lid & 15)) * ROWB + (uint32_t)(lid >> 4) * 16;

    const int nchunks = lda / 64;              // 20
    for (int c = 0; c < nchunks; c++) {
        const int buf = c % 3;
        cp_wait<1>();
        __syncthreads();
        if (c + 3 <= nchunks - 1 + 1 && c + 2 < nchunks) issue_tile(c + 2, (c + 2) % 3);
        else cp_commit();

        const uint32_t As = sbase + buf * STAGE + a_lane;
        const uint32_t Bs = sbase + buf * STAGE + A_BYTES + b_lane;

        #pragma unroll
        for (int kk = 0; kk < 4; kk++) {
            uint32_t bf_[4][2];
            #pragma unroll
            for (int j = 0; j < 2; j++) {
                uint32_t r0, r1, r2, r3;
                ldsm_x4(r0, r1, r2, r3, Bs + j * 16 * ROWB + kk * 32);
                bf_[j * 2 + 0][0] = r0; bf_[j * 2 + 0][1] = r2;
                bf_[j * 2 + 1][0] = r1; bf_[j * 2 + 1][1] = r3;
            }
            uint32_t af[4][4];
            #pragma unroll
            for (int mi = 0; mi < 4; mi++)
                ldsm_x4(af[mi][0], af[mi][1], af[mi][2], af[mi][3],
                        As + mi * 16 * ROWB + kk * 32);
            #pragma unroll
            for (int mi = 0; mi < 4; mi++)
                #pragma unroll
                for (int ni = 0; ni < 4; ni++)
                    mma16816(acc[mi][ni], af[mi], bf_[ni]);
        }
    }

    // all warps done with mainloop buffers before smem reuse
    cp_wait<0>();
    __syncthreads();

    // prefetch W2' (128 x 256, row 512B -> stride 528) and W3' (64 x 128 -> 272)
    {
        #pragma unroll
        for (int i = 0; i < 8; i++) {
            int idx = tid + i * THREADS;               // 4096 chunks
            int row = idx >> 5, ch = idx & 31;
            cp_async16(sbase + SM_W2 + row * 528 + ch * 16,
                       w2t + (size_t)row * H1 + ch * 8);
        }
        #pragma unroll
        for (int i = 0; i < 2; i++) {
            int idx = tid + i * THREADS;               // 1024 chunks
            int row = idx >> 4, ch = idx & 15;
            cp_async16(sbase + SM_W3 + row * 272 + ch * 16,
                       w3t + (size_t)row * H2 + ch * 8);
        }
        cp_commit();
    }
    // head weights to smem
    {
        float* hw = reinterpret_cast<float*>(smem + SM_HEAD);
        if (tid < 66)  hw[tid] = Wc[tid];
        if (tid >= 256 && tid < 322) hw[66 + tid - 256] = Wo[tid - 256];
    }

    // h1 fragments -> smem (relu + b1), stride 264 halves
    {
        __half* h1p = reinterpret_cast<__half*>(smem + SM_H1);
        #pragma unroll
        for (int mi = 0; mi < 4; mi++) {
            #pragma unroll
            for (int ni = 0; ni < 4; ni++) {
                const int m0 = wm * 64 + mi * 16 + (lid >> 2);
                const int n0 = wn * 32 + ni * 8 + (lid & 3) * 2;
                const float c0 = __ldg(&b1[n0]);
                const float c1 = __ldg(&b1[n0 + 1]);
                __half2 p0, p1;
                p0.x = __float2half(fmaxf(acc[mi][ni][0] + c0, 0.0f));
                p0.y = __float2half(fmaxf(acc[mi][ni][1] + c1, 0.0f));
                p1.x = __float2half(fmaxf(acc[mi][ni][2] + c0, 0.0f));
                p1.y = __float2half(fmaxf(acc[mi][ni][3] + c1, 0.0f));
                *reinterpret_cast<__half2*>(&h1p[m0 * 264 + n0]) = p0;
                *reinterpret_cast<__half2*>(&h1p[(m0 + 8) * 264 + n0]) = p1;
            }
        }
    }
    cp_wait<0>();
    __syncthreads();

    // ---------------- stage 2: h2 = relu(h1 @ W2 + b2), K=256 ----------------
    {
        const int wm2 = wid >> 3;              // 0..1, 64 rows
        const int wn2 = wid & 7;               // 0..7, 16 cols
        const uint32_t a2 = sbase + SM_H1 +
            (uint32_t)(wm2 * 64 + (lid & 15)) * 528 + (uint32_t)(lid >> 4) * 16;
        const uint32_t b2s = sbase + SM_W2 +
            (uint32_t)(wn2 * 16 + (lid & 15)) * 528 + (uint32_t)(lid >> 4) * 16;

        float acc2[4][2][4];
        #pragma unroll
        for (int i = 0; i < 4; i++)
            #pragma unroll
            for (int j = 0; j < 2; j++)
                #pragma unroll
                for (int k = 0; k < 4; k++) acc2[i][j][k] = 0.0f;

        #pragma unroll
        for (int kk = 0; kk < 16; kk++) {
            uint32_t r0, r1, r2, r3;
            ldsm_x4(r0, r1, r2, r3, b2s + kk * 32);
            uint32_t bf0[2] = {r0, r2};
            uint32_t bf1[2] = {r1, r3};
            #pragma unroll
            for (int mi = 0; mi < 4; mi++) {
                uint32_t af[4];
                ldsm_x4(af[0], af[1], af[2], af[3], a2 + mi * 16 * 528 + kk * 32);
                mma16816(acc2[mi][0], af, bf0);
                mma16816(acc2[mi][1], af, bf1);
            }
        }

        __half* h2p = reinterpret_cast<__half*>(smem + SM_H2);
        #pragma unroll
        for (int mi = 0; mi < 4; mi++) {
            #pragma unroll
            for (int ni = 0; ni < 2; ni++) {
                const int m0 = wm2 * 64 + mi * 16 + (lid >> 2);
                const int n0 = wn2 * 16 + ni * 8 + (lid & 3) * 2;
                const float c0 = __ldg(&b2[n0]);
                const float c1 = __ldg(&b2[n0 + 1]);
                __half2 p0, p1;
                p0.x = __float2half(fmaxf(acc2[mi][ni][0] + c0, 0.0f));
                p0.y = __float2half(fmaxf(acc2[mi][ni][1] + c1, 0.0f));
                p1.x = __float2half(fmaxf(acc2[mi][ni][2] + c0, 0.0f));
                p1.y = __float2half(fmaxf(acc2[mi][ni][3] + c1, 0.0f));
                *reinterpret_cast<__half2*>(&h2p[m0 * 136 + n0]) = p0;
                *reinterpret_cast<__half2*>(&h2p[(m0 + 8) * 136 + n0]) = p1;
            }
        }
    }
    __syncthreads();

    // ---------------- stage 3: h3 = relu(h2 @ W3 + b3), K=128 ----------------
    {
        const int wm3 = wid >> 2;              // 0..3, 32 rows
        const int wn3 = wid & 3;               // 0..3, 16 cols
        const uint32_t a3 = sbase + SM_H2 +
            (uint32_t)(wm3 * 32 + (lid & 15)) * 272 + (uint32_t)(lid >> 4) * 16;
        const uint32_t b3s = sbase + SM_W3 +
            (uint32_t)(wn3 * 16 + (lid & 15)) * 272 + (uint32_t)(lid >> 4) * 16;

        float acc3[2][2][4];
        #pragma unroll
        for (int i = 0; i < 2; i++)
            #pragma unroll
            for (int j = 0; j < 2; j++)
                #pragma unroll
                for (int k = 0; k < 4; k++) acc3[i][j][k] = 0.0f;

        #pragma unroll
        for (int kk = 0; kk < 8; kk++) {
            uint32_t r0, r1, r2, r3;
            ldsm_x4(r0, r1, r2, r3, b3s + kk * 32);
            uint32_t bf0[2] = {r0, r2};
            uint32_t bf1[2] = {r1, r3};
            #pragma unroll
            for (int mi = 0; mi < 2; mi++) {
                uint32_t af[4];
                ldsm_x4(af[0], af[1], af[2], af[3], a3 + mi * 16 * 272 + kk * 32);
                mma16816(acc3[mi][0], af, bf0);
                mma16816(acc3[mi][1], af, bf1);
            }
        }

        float* h3p = reinterpret_cast<float*>(smem + SM_H3);
        #pragma unroll
        for (int mi = 0; mi < 2; mi++) {
            #pragma unroll
            for (int ni = 0; ni < 2; ni++) {
                const int m0 = wm3 * 32 + mi * 16 + (lid >> 2);
                const int n0 = wn3 * 16 + ni * 8 + (lid & 3) * 2;
                const float c0 = __ldg(&b3[n0]);
                const float c1 = __ldg(&b3[n0 + 1]);
                *reinterpret_cast<float2*>(&h3p[m0 * 68 + n0]) = make_float2(
                    fmaxf(acc3[mi][ni][0] + c0, 0.0f), fmaxf(acc3[mi][ni][1] + c1, 0.0f));
                *reinterpret_cast<float2*>(&h3p[(m0 + 8) * 68 + n0]) = make_float2(
                    fmaxf(acc3[mi][ni][2] + c0, 0.0f), fmaxf(acc3[mi][ni][3] + c1, 0.0f));
            }
        }
    }
    __syncthreads();

    // ---------------- head ----------------
    if (tid < 128) {
        const float* h3p = reinterpret_cast<const float*>(smem + SM_H3) + tid * 68;
        const float* hw  = reinterpret_cast<const float*>(smem + SM_HEAD);
        float dc = 0.0f, dw = 0.0f;
        #pragma unroll
        for (int c = 0; c < H3; c++) {
            float v = h3p[c];
            dc += v * hw[c];
            dw += v * hw[66 + c];
        }
        const int r = mrow0 + tid;
        const float l = lin[r], f = fm[r];
        out[r]          = dc + l * hw[64] + f * hw[65] + __ldg(&bc[0]);
        out[B_ROWS + r] = dw + l * hw[66 + 64] + f * hw[66 + 65] + __ldg(&bo[0]);
    }
}

// ---------------- launch ----------------
extern "C" void kernel_launch(void* const* d_in, const int* in_sizes, int n_in,
                              void* d_out, int out_size)
{
    const int*   x_cat    = (const int*)  d_in[0];
    const float* x_num    = (const float*)d_in[1];
    const float* emb0     = (const float*)d_in[2];
    const float* emb1     = (const float*)d_in[3];
    const float* num_bias = (const float*)d_in[4];
    const float* num_emb  = (const float*)d_in[5];
    const float* W1 = (const float*)d_in[6];
    const float* b1 = (const float*)d_in[7];
    const float* W2 = (const float*)d_in[8];
    const float* b2 = (const float*)d_in[9];
    const float* W3 = (const float*)d_in[10];
    const float* b3 = (const float*)d_in[11];
    const float* Wc = (const float*)d_in[12];
    const float* bc = (const float*)d_in[13];
    const float* Wo = (const float*)d_in[14];
    const float* bo = (const float*)d_in[15];
    float* out = (float*)d_out;

    unsigned char* base = nullptr;
    cudaGetSymbolAddress((void**)&base, g_scratch);
    __half* e    = (__half*)(base + OFF_E);
    __half* w1t  = (__half*)(base + OFF_W1T);
    __half* w2t  = (__half*)(base + OFF_W2T);
    __half* w3t  = (__half*)(base + OFF_W3T);
    float*  lin  = (float*)(base + OFF_LIN);
    float*  fm   = (float*)(base + OFF_FM);

    cudaFuncSetAttribute(mega_mlp,
                         cudaFuncAttributeMaxDynamicSharedMemorySize, SMEM_MEGA);

    // 0) weight prep (one launch, all three transposed fp16 tiles)
    {
        const int tot = H1 * K1P + H2 * H1 + H3 * H2;
        prep_all<<<(tot + 255) / 256, 256>>>(W1, w1t, W2, w2t, W3, w3t);
    }

    // 1) embedding gather + FM/linear (fp16 output)
    embed_kernel<<<B_ROWS / 8, 256>>>(x_cat, x_num, emb0, emb1, num_bias,
                                      num_emb, e, lin, fm);

    // 2) fused MLP + head
    mega_mlp<<<dim3(1, B_ROWS / 128), 512, SMEM_MEGA>>>(
        e, w1t, w2t, w3t, b1, b2, b3, Wc, bc, Wo, bo, lin, fm, out);
}

// round 9
// speedup vs baseline: 5.3813x; 1.0927x over previous
#include <cuda_runtime.h>
#include <cuda_fp16.h>
#include <cstdint>
#include <cstddef>

// ---------------- problem constants ----------------
#define B_ROWS 16384
#define F_CAT  26
#define N_NUM  13
#define VOCAB  100000
#define K1     1248
#define K1P    1280   // padded: 40 features x 32 dims (39 real + 1 pad)
#define H1     256
#define H2     128
#define H3     64

// ---------------- scratch (static device memory): weights only -------------
constexpr size_t ALN(size_t x) { return (x + 255) & ~(size_t)255; }
constexpr size_t OFF_W1T = 0;                                     // [256][1280] fp16
constexpr size_t OFF_W2T = ALN(OFF_W1T + (size_t)H1 * K1P * 2);   // [128][256]
constexpr size_t OFF_W3T = ALN(OFF_W2T + (size_t)H2 * H1 * 2);    // [64][128]
constexpr size_t TOTAL_SCRATCH = ALN(OFF_W3T + (size_t)H3 * H2 * 2);
__device__ __align__(256) unsigned char g_scratch[TOTAL_SCRATCH];

// ---------------- smem layout (bytes) ----------------
// mainloop: 3 stages x (A 128x144 + B 256x144) = 165888 at offset 0
#define ROWB      144
#define A_BYTES   (128 * ROWB)            // 18432
#define STAGE     ((128 + 256) * ROWB)    // 55296
#define SM_IDS    165888                  // int   [128][26] = 13312
#define SM_XNUM   179200                  // float [128][13] = 6656
#define SM_NEMB   185856                  // float [13][32]  = 1664
// post-mainloop reuse:
#define SM_H1     0                       // h1 [128][264 halves] stride 528
#define SM_W2     69632                   // W2' [128][264 halves] stride 528
#define SM_H2     139264                  // h2 [128][136 halves] stride 272
#define SM_W3     174336                  // W3' [64][136 halves] stride 272
#define SM_H3     192000                  // h3 [128][68 floats]  stride 272
#define SM_HEAD   226816                  // Wc(66 f32) | Wo(66 f32)
#define SM_LINP   227344                  // float [128][4]
#define SM_FMP    229392                  // float [128][4]
#define SMEM_MEGA 231440

// ---------------- PTX helpers (sm_80-compatible; no 'a' features) ----------
__device__ __forceinline__ uint32_t smem_to_u32(const void* p) {
    uint32_t a;
    asm("{ .reg .u64 t; cvta.to.shared.u64 t, %1; cvt.u32.u64 %0, t; }" : "=r"(a) : "l"(p));
    return a;
}
__device__ __forceinline__ void cp_async16(uint32_t saddr, const void* gaddr) {
    asm volatile("cp.async.cg.shared.global [%0], [%1], 16;"
                 :: "r"(saddr), "l"(gaddr) : "memory");
}
__device__ __forceinline__ void cp_commit() {
    asm volatile("cp.async.commit_group;" ::: "memory");
}
template<int N>
__device__ __forceinline__ void cp_wait() {
    asm volatile("cp.async.wait_group %0;" :: "n"(N) : "memory");
}
__device__ __forceinline__ void ldsm_x4(uint32_t& r0, uint32_t& r1,
                                        uint32_t& r2, uint32_t& r3, uint32_t addr) {
    asm volatile("ldmatrix.sync.aligned.m8n8.x4.shared.b16 {%0,%1,%2,%3}, [%4];"
                 : "=r"(r0), "=r"(r1), "=r"(r2), "=r"(r3) : "r"(addr));
}
__device__ __forceinline__ void mma16816(float* d, const uint32_t* a, const uint32_t* b) {
    asm volatile(
        "mma.sync.aligned.m16n8k16.row.col.f32.f16.f16.f32 "
        "{%0,%1,%2,%3}, {%4,%5,%6,%7}, {%8,%9}, {%0,%1,%2,%3};"
        : "+f"(d[0]), "+f"(d[1]), "+f"(d[2]), "+f"(d[3])
        : "r"(a[0]), "r"(a[1]), "r"(a[2]), "r"(a[3]), "r"(b[0]), "r"(b[1]));
}

// ---------------- prep: all three transposed fp16 weight tiles ----------
__global__ void prep_all(const float* __restrict__ W1, __half* __restrict__ o1,
                         const float* __restrict__ W2, __half* __restrict__ o2,
                         const float* __restrict__ W3, __half* __restrict__ o3)
{
    int idx = blockIdx.x * blockDim.x + threadIdx.x;
    const int T1 = H1 * K1P;
    const int T2 = H2 * H1;
    const int T3 = H3 * H2;
    if (idx < T1) {
        int n = idx / K1P, c = idx % K1P;
        o1[idx] = (c < K1) ? __float2half(W1[(size_t)c * H1 + n]) : __float2half(0.0f);
    } else if (idx < T1 + T2) {
        int r = idx - T1;
        int n = r / H1, c = r % H1;
        o2[r] = __float2half(W2[(size_t)c * H2 + n]);
    } else if (idx < T1 + T2 + T3) {
        int r = idx - T1 - T2;
        int n = r / H2, c = r % H2;
        o3[r] = __float2half(W3[(size_t)c * H3 + n]);   // W3 stride is H3 (FIXED)
    }
}

// 8 fp32 values of one feature at d in [q*8, q*8+8)
struct A8 { float4 a, b; };

// ---------------- megakernel: gather + FM + full MLP + head ----------------
__global__ __launch_bounds__(512)
void mega_mlp(const int*   __restrict__ x_cat,
              const float* __restrict__ x_num,
              const float* __restrict__ emb0,
              const float* __restrict__ emb1,
              const float* __restrict__ num_bias,
              const float* __restrict__ num_emb,
              const __half* __restrict__ w1t,
              const __half* __restrict__ w2t,
              const __half* __restrict__ w3t,
              const float* __restrict__ b1,
              const float* __restrict__ b2,
              const float* __restrict__ b3,
              const float* __restrict__ Wc, const float* __restrict__ bc,
              const float* __restrict__ Wo, const float* __restrict__ bo,
              float* __restrict__ out)
{
    constexpr int THREADS = 512;
    constexpr int lda     = K1P;
    constexpr int nchunks = K1P / 64;          // 20 (2 features per chunk)

    extern __shared__ unsigned char smem[];
    const uint32_t sbase = smem_to_u32(smem);

    const int tid = threadIdx.x;
    const int wid = tid >> 5;
    const int lid = tid & 31;
    const int mrow0 = blockIdx.y * 128;

    int*   s_ids  = reinterpret_cast<int*>(smem + SM_IDS);
    float* s_xnum = reinterpret_cast<float*>(smem + SM_XNUM);
    float* s_nemb = reinterpret_cast<float*>(smem + SM_NEMB);
    float* s_linp = reinterpret_cast<float*>(smem + SM_LINP);
    float* s_fmp  = reinterpret_cast<float*>(smem + SM_FMP);

    // ---------- B (W1') pipeline ----------
    const int b_r = tid >> 3, b_c = tid & 7;   // row-in-pass, 16B chunk
    const uint32_t bsm_off = (uint32_t)b_r * ROWB + (uint32_t)b_c * 16;
    const __half* wrow = w1t + (size_t)b_r * lda + b_c * 8;
    auto issue_B = [&](int c, int buf) {
        const int kc = c * 64;
        uint32_t Bs = sbase + buf * STAGE + A_BYTES;
        #pragma unroll
        for (int i = 0; i < 4; i++)
            cp_async16(Bs + bsm_off + i * 64 * ROWB, wrow + (size_t)i * 64 * lda + kc);
    };

    // ---------- A gather mapping: r = tid>>2 (128 rows), q = tid&3 ----------
    const int g_r = tid >> 2;
    const int g_q = tid & 3;

    // FM accumulators: this thread sees ALL features at its 8 d-positions
    float fmsum[8] = {0, 0, 0, 0, 0, 0, 0, 0};
    float sqtot = 0.0f;

    auto fetch_feat = [&](int f) -> A8 {
        A8 o;
        if (f < F_CAT) {
            int id = s_ids[g_r * F_CAT + f];
            const float4* p = reinterpret_cast<const float4*>(
                emb1 + ((size_t)f * VOCAB + id) * 32 + g_q * 8);
            o.a = p[0]; o.b = p[1];
        } else if (f < F_CAT + N_NUM) {
            int n = f - F_CAT;
            float xv = s_xnum[g_r * N_NUM + n];
            const float4* p = reinterpret_cast<const float4*>(s_nemb + n * 32 + g_q * 8);
            float4 e0 = p[0], e1 = p[1];
            o.a = make_float4(xv * e0.x, xv * e0.y, xv * e0.z, xv * e0.w);
            o.b = make_float4(xv * e1.x, xv * e1.y, xv * e1.z, xv * e1.w);
        } else {
            o.a = make_float4(0, 0, 0, 0);
            o.b = make_float4(0, 0, 0, 0);
        }
        return o;
    };
    // accumulate FM + convert + store 16B into A stage (half = 0 for f0, 1 for f1)
    auto store_feat = [&](const A8& v, int buf, int half) {
        fmsum[0] += v.a.x; fmsum[1] += v.a.y; fmsum[2] += v.a.z; fmsum[3] += v.a.w;
        fmsum[4] += v.b.x; fmsum[5] += v.b.y; fmsum[6] += v.b.z; fmsum[7] += v.b.w;
        sqtot += v.a.x * v.a.x + v.a.y * v.a.y + v.a.z * v.a.z + v.a.w * v.a.w
               + v.b.x * v.b.x + v.b.y * v.b.y + v.b.z * v.b.z + v.b.w * v.b.w;
        __half2 h0 = __floats2half2_rn(v.a.x, v.a.y);
        __half2 h1 = __floats2half2_rn(v.a.z, v.a.w);
        __half2 h2 = __floats2half2_rn(v.b.x, v.b.y);
        __half2 h3 = __floats2half2_rn(v.b.z, v.b.w);
        uint4 u;
        u.x = *reinterpret_cast<uint32_t*>(&h0);
        u.y = *reinterpret_cast<uint32_t*>(&h1);
        u.z = *reinterpret_cast<uint32_t*>(&h2);
        u.w = *reinterpret_cast<uint32_t*>(&h3);
        *reinterpret_cast<uint4*>(smem + buf * STAGE + g_r * ROWB + half * 64 + g_q * 16) = u;
    };

    // ---------- prologue ----------
    issue_B(0, 0); cp_commit();
    issue_B(1, 1); cp_commit();

    // preload ids / x_num / num_emb
    for (int i = tid; i < 128 * F_CAT; i += THREADS)
        s_ids[i] = x_cat[(size_t)(mrow0 + i / F_CAT) * F_CAT + (i % F_CAT)];
    for (int i = tid; i < 128 * N_NUM; i += THREADS)
        s_xnum[i] = x_num[(size_t)(mrow0 + i / N_NUM) * N_NUM + (i % N_NUM)];
    for (int i = tid; i < N_NUM * 32; i += THREADS)
        s_nemb[i] = num_emb[i];
    __syncthreads();

    // linear-term partials (4 per row)
    {
        float lp = 0.0f;
        for (int f = g_q; f < F_CAT; f += 4)
            lp += __ldg(emb0 + (size_t)f * VOCAB + s_ids[g_r * F_CAT + f]);
        if (g_q == 0) {
            #pragma unroll
            for (int n = 0; n < N_NUM; n++)
                lp += s_xnum[g_r * N_NUM + n] * __ldg(num_bias + n);
        }
        s_linp[g_r * 4 + g_q] = lp;
    }
    // stage A chunks 0 and 1
    {
        A8 v0 = fetch_feat(0), v1 = fetch_feat(1);
        store_feat(v0, 0, 0); store_feat(v1, 0, 1);
        A8 v2 = fetch_feat(2), v3 = fetch_feat(3);
        store_feat(v2, 1, 0); store_feat(v3, 1, 1);
    }
    __syncthreads();

    // ---------- mainloop ----------
    float acc[4][4][4];
    #pragma unroll
    for (int i = 0; i < 4; i++)
        #pragma unroll
        for (int j = 0; j < 4; j++)
            #pragma unroll
            for (int k = 0; k < 4; k++) acc[i][j][k] = 0.0f;

    const int wm = wid >> 3;                   // 0..1
    const int wn = wid & 7;                    // 0..7
    const uint32_t a_lane = (uint32_t)(wm * 64 + (lid & 15)) * ROWB + (uint32_t)(lid >> 4) * 16;
    const uint32_t b_lane = (uint32_t)(wn * 32 + (lid & 15)) * ROWB + (uint32_t)(lid >> 4) * 16;

    for (int c = 0; c < nchunks; c++) {
        const int buf = c % 3;
        cp_wait<1>();
        __syncthreads();

        const bool has = (c + 2 < nchunks);
        const int nbuf = (c + 2) % 3;
        if (has) issue_B(c + 2, nbuf);
        cp_commit();

        A8 v0, v1;
        if (has) { v0 = fetch_feat(2 * (c + 2)); v1 = fetch_feat(2 * (c + 2) + 1); }

        const uint32_t As = sbase + buf * STAGE + a_lane;
        const uint32_t Bs = sbase + buf * STAGE + A_BYTES + b_lane;
        #pragma unroll
        for (int kk = 0; kk < 4; kk++) {
            uint32_t bf_[4][2];
            #pragma unroll
            for (int j = 0; j < 2; j++) {
                uint32_t r0, r1, r2, r3;
                ldsm_x4(r0, r1, r2, r3, Bs + j * 16 * ROWB + kk * 32);
                bf_[j * 2 + 0][0] = r0; bf_[j * 2 + 0][1] = r2;
                bf_[j * 2 + 1][0] = r1; bf_[j * 2 + 1][1] = r3;
            }
            uint32_t af[4][4];
            #pragma unroll
            for (int mi = 0; mi < 4; mi++)
                ldsm_x4(af[mi][0], af[mi][1], af[mi][2], af[mi][3],
                        As + mi * 16 * ROWB + kk * 32);
            #pragma unroll
            for (int mi = 0; mi < 4; mi++)
                #pragma unroll
                for (int ni = 0; ni < 4; ni++)
                    mma16816(acc[mi][ni], af[mi], bf_[ni]);
        }

        if (has) { store_feat(v0, nbuf, 0); store_feat(v1, nbuf, 1); }
    }

    // FM partials (all features seen; finalize per thread)
    {
        float p = -sqtot;
        #pragma unroll
        for (int j = 0; j < 8; j++) p += fmsum[j] * fmsum[j];
        s_fmp[g_r * 4 + g_q] = p;
    }

    cp_wait<0>();
    __syncthreads();

    // prefetch W2' (128 x 256 -> stride 528) and W3' (64 x 128 -> stride 272)
    {
        #pragma unroll
        for (int i = 0; i < 8; i++) {
            int idx = tid + i * THREADS;
            int row = idx >> 5, ch = idx & 31;
            cp_async16(sbase + SM_W2 + row * 528 + ch * 16,
                       w2t + (size_t)row * H1 + ch * 8);
        }
        #pragma unroll
        for (int i = 0; i < 2; i++) {
            int idx = tid + i * THREADS;
            int row = idx >> 4, ch = idx & 15;
            cp_async16(sbase + SM_W3 + row * 272 + ch * 16,
                       w3t + (size_t)row * H2 + ch * 8);
        }
        cp_commit();
    }
    {
        float* hw = reinterpret_cast<float*>(smem + SM_HEAD);
        if (tid < 66)  hw[tid] = Wc[tid];
        if (tid >= 256 && tid < 322) hw[66 + tid - 256] = Wo[tid - 256];
    }

    // h1 fragments -> smem (relu + b1)
    {
        __half* h1p = reinterpret_cast<__half*>(smem + SM_H1);
        #pragma unroll
        for (int mi = 0; mi < 4; mi++) {
            #pragma unroll
            for (int ni = 0; ni < 4; ni++) {
                const int m0 = wm * 64 + mi * 16 + (lid >> 2);
                const int n0 = wn * 32 + ni * 8 + (lid & 3) * 2;
                const float c0 = __ldg(&b1[n0]);
                const float c1 = __ldg(&b1[n0 + 1]);
                __half2 p0, p1;
                p0.x = __float2half(fmaxf(acc[mi][ni][0] + c0, 0.0f));
                p0.y = __float2half(fmaxf(acc[mi][ni][1] + c1, 0.0f));
                p1.x = __float2half(fmaxf(acc[mi][ni][2] + c0, 0.0f));
                p1.y = __float2half(fmaxf(acc[mi][ni][3] + c1, 0.0f));
                *reinterpret_cast<__half2*>(&h1p[m0 * 264 + n0]) = p0;
                *reinterpret_cast<__half2*>(&h1p[(m0 + 8) * 264 + n0]) = p1;
            }
        }
    }
    cp_wait<0>();
    __syncthreads();

    // ---------- stage 2: h2 = relu(h1 @ W2 + b2), K=256 ----------
    {
        const int wm2 = wid >> 3;
        const int wn2 = wid & 7;
        const uint32_t a2 = sbase + SM_H1 +
            (uint32_t)(wm2 * 64 + (lid & 15)) * 528 + (uint32_t)(lid >> 4) * 16;
        const uint32_t b2s = sbase + SM_W2 +
            (uint32_t)(wn2 * 16 + (lid & 15)) * 528 + (uint32_t)(lid >> 4) * 16;

        float acc2[4][2][4];
        #pragma unroll
        for (int i = 0; i < 4; i++)
            #pragma unroll
            for (int j = 0; j < 2; j++)
                #pragma unroll
                for (int k = 0; k < 4; k++) acc2[i][j][k] = 0.0f;

        #pragma unroll
        for (int kk = 0; kk < 16; kk++) {
            uint32_t r0, r1, r2, r3;
            ldsm_x4(r0, r1, r2, r3, b2s + kk * 32);
            uint32_t bf0[2] = {r0, r2};
            uint32_t bf1[2] = {r1, r3};
            #pragma unroll
            for (int mi = 0; mi < 4; mi++) {
                uint32_t af[4];
                ldsm_x4(af[0], af[1], af[2], af[3], a2 + mi * 16 * 528 + kk * 32);
                mma16816(acc2[mi][0], af, bf0);
                mma16816(acc2[mi][1], af, bf1);
            }
        }

        __half* h2p = reinterpret_cast<__half*>(smem + SM_H2);
        #pragma unroll
        for (int mi = 0; mi < 4; mi++) {
            #pragma unroll
            for (int ni = 0; ni < 2; ni++) {
                const int m0 = wm2 * 64 + mi * 16 + (lid >> 2);
                const int n0 = wn2 * 16 + ni * 8 + (lid & 3) * 2;
                const float c0 = __ldg(&b2[n0]);
                const float c1 = __ldg(&b2[n0 + 1]);
                __half2 p0, p1;
                p0.x = __float2half(fmaxf(acc2[mi][ni][0] + c0, 0.0f));
                p0.y = __float2half(fmaxf(acc2[mi][ni][1] + c1, 0.0f));
                p1.x = __float2half(fmaxf(acc2[mi][ni][2] + c0, 0.0f));
                p1.y = __float2half(fmaxf(acc2[mi][ni][3] + c1, 0.0f));
                *reinterpret_cast<__half2*>(&h2p[m0 * 136 + n0]) = p0;
                *reinterpret_cast<__half2*>(&h2p[(m0 + 8) * 136 + n0]) = p1;
            }
        }
    }
    __syncthreads();

    // ---------- stage 3: h3 = relu(h2 @ W3 + b3), K=128 ----------
    {
        const int wm3 = wid >> 2;
        const int wn3 = wid & 3;
        const uint32_t a3 = sbase + SM_H2 +
            (uint32_t)(wm3 * 32 + (lid & 15)) * 272 + (uint32_t)(lid >> 4) * 16;
        const uint32_t b3s = sbase + SM_W3 +
            (uint32_t)(wn3 * 16 + (lid & 15)) * 272 + (uint32_t)(lid >> 4) * 16;

        float acc3[2][2][4];
        #pragma unroll
        for (int i = 0; i < 2; i++)
            #pragma unroll
            for (int j = 0; j < 2; j++)
                #pragma unroll
                for (int k = 0; k < 4; k++) acc3[i][j][k] = 0.0f;

        #pragma unroll
        for (int kk = 0; kk < 8; kk++) {
            uint32_t r0, r1, r2, r3;
            ldsm_x4(r0, r1, r2, r3, b3s + kk * 32);
            uint32_t bf0[2] = {r0, r2};
            uint32_t bf1[2] = {r1, r3};
            #pragma unroll
            for (int mi = 0; mi < 2; mi++) {
                uint32_t af[4];
                ldsm_x4(af[0], af[1], af[2], af[3], a3 + mi * 16 * 272 + kk * 32);
                mma16816(acc3[mi][0], af, bf0);
                mma16816(acc3[mi][1], af, bf1);
            }
        }

        float* h3p = reinterpret_cast<float*>(smem + SM_H3);
        #pragma unroll
        for (int mi = 0; mi < 2; mi++) {
            #pragma unroll
            for (int ni = 0; ni < 2; ni++) {
                const int m0 = wm3 * 32 + mi * 16 + (lid >> 2);
                const int n0 = wn3 * 16 + ni * 8 + (lid & 3) * 2;
                const float c0 = __ldg(&b3[n0]);
                const float c1 = __ldg(&b3[n0 + 1]);
                *reinterpret_cast<float2*>(&h3p[m0 * 68 + n0]) = make_float2(
                    fmaxf(acc3[mi][ni][0] + c0, 0.0f), fmaxf(acc3[mi][ni][1] + c1, 0.0f));
                *reinterpret_cast<float2*>(&h3p[(m0 + 8) * 68 + n0]) = make_float2(
                    fmaxf(acc3[mi][ni][2] + c0, 0.0f), fmaxf(acc3[mi][ni][3] + c1, 0.0f));
            }
        }
    }
    __syncthreads();

    // ---------- head ----------
    if (tid < 128) {
        const float* h3p = reinterpret_cast<const float*>(smem + SM_H3) + tid * 68;
        const float* hw  = reinterpret_cast<const float*>(smem + SM_HEAD);
        float dc = 0.0f, dw = 0.0f;
        #pragma unroll
        for (int c = 0; c < H3; c++) {
            float v = h3p[c];
            dc += v * hw[c];
            dw += v * hw[66 + c];
        }
        const float l = s_linp[tid * 4] + s_linp[tid * 4 + 1]
                      + s_linp[tid * 4 + 2] + s_linp[tid * 4 + 3];
        const float f = 0.5f * (s_fmp[tid * 4] + s_fmp[tid * 4 + 1]
                              + s_fmp[tid * 4 + 2] + s_fmp[tid * 4 + 3]);
        const int r = mrow0 + tid;
        out[r]          = dc + l * hw[64] + f * hw[65] + __ldg(&bc[0]);
        out[B_ROWS + r] = dw + l * hw[66 + 64] + f * hw[66 + 65] + __ldg(&bo[0]);
    }
}

// ---------------- launch ----------------
extern "C" void kernel_launch(void* const* d_in, const int* in_sizes, int n_in,
                              void* d_out, int out_size)
{
    const int*   x_cat    = (const int*)  d_in[0];
    const float* x_num    = (const float*)d_in[1];
    const float* emb0     = (const float*)d_in[2];
    const float* emb1     = (const float*)d_in[3];
    const float* num_bias = (const float*)d_in[4];
    const float* num_emb  = (const float*)d_in[5];
    const float* W1 = (const float*)d_in[6];
    const float* b1 = (const float*)d_in[7];
    const float* W2 = (const float*)d_in[8];
    const float* b2 = (const float*)d_in[9];
    const float* W3 = (const float*)d_in[10];
    const float* b3 = (const float*)d_in[11];
    const float* Wc = (const float*)d_in[12];
    const float* bc = (const float*)d_in[13];
    const float* Wo = (const float*)d_in[14];
    const float* bo = (const float*)d_in[15];
    float* out = (float*)d_out;

    unsigned char* base = nullptr;
    cudaGetSymbolAddress((void**)&base, g_scratch);
    __half* w1t = (__half*)(base + OFF_W1T);
    __half* w2t = (__half*)(base + OFF_W2T);
    __half* w3t = (__half*)(base + OFF_W3T);

    cudaFuncSetAttribute(mega_mlp,
                         cudaFuncAttributeMaxDynamicSharedMemorySize, SMEM_MEGA);

    // 0) weight prep
    {
        const int tot = H1 * K1P + H2 * H1 + H3 * H2;
        prep_all<<<(tot + 255) / 256, 256>>>(W1, w1t, W2, w2t, W3, w3t);
    }

    // 1) fused gather + FM + MLP + head
    mega_mlp<<<dim3(1, B_ROWS / 128), 512, SMEM_MEGA>>>(
        x_cat, x_num, emb0, emb1, num_bias, num_emb,
        w1t, w2t, w3t, b1, b2, b3, Wc, bc, Wo, bo, out);
}